// round 4
// baseline (speedup 1.0000x reference)
#include <cuda_runtime.h>
#include <cuda_bf16.h>
#include <cstdint>

// Problem constants
#define BB 2
#define TT 2048
#define DD 1024
#define HH 16
#define DH 64
#define MM (BB*TT)          // 4096
#define N_QKV (3*DD)        // 3072

// Scratch (device globals — no runtime allocation allowed)
__device__ float gQ[BB*HH*TT*DH];   // [B,H,T,dh]
__device__ float gK[BB*HH*TT*DH];
__device__ float gV[BB*HH*TT*DH];
__device__ float gA[BB*TT*DD];      // merged-head attention output [B,T,D]

// ---------------------------------------------------------------------------
// Helpers (baseline PTX only: ldmatrix + mma.sync, sm_75/80 features)
// ---------------------------------------------------------------------------
__device__ __forceinline__ uint32_t smem_u32(const void* p) {
    uint32_t a;
    asm("{ .reg .u64 t; cvta.to.shared.u64 t, %1; cvt.u32.u64 %0, t; }"
        : "=r"(a) : "l"(p));
    return a;
}

__device__ __forceinline__ void ldm_x4(uint32_t* r, uint32_t addr) {
    asm volatile("ldmatrix.sync.aligned.m8n8.x4.shared.b16 {%0,%1,%2,%3}, [%4];"
                 : "=r"(r[0]), "=r"(r[1]), "=r"(r[2]), "=r"(r[3]) : "r"(addr));
}

__device__ __forceinline__ void ldm_x2t(uint32_t* r, uint32_t addr) {
    asm volatile("ldmatrix.sync.aligned.m8n8.x2.trans.shared.b16 {%0,%1}, [%2];"
                 : "=r"(r[0]), "=r"(r[1]) : "r"(addr));
}

__device__ __forceinline__ void mma_bf16(float* c, const uint32_t* a, const uint32_t* b) {
    asm volatile(
        "mma.sync.aligned.m16n8k16.row.col.f32.bf16.bf16.f32 "
        "{%0,%1,%2,%3}, {%4,%5,%6,%7}, {%8,%9}, {%0,%1,%2,%3};"
        : "+f"(c[0]), "+f"(c[1]), "+f"(c[2]), "+f"(c[3])
        : "r"(a[0]), "r"(a[1]), "r"(a[2]), "r"(a[3]), "r"(b[0]), "r"(b[1]));
}

__device__ __forceinline__ uint32_t pack_bf2(__nv_bfloat16 a, __nv_bfloat16 b) {
    __nv_bfloat162 t(a, b);
    return *reinterpret_cast<uint32_t*>(&t);
}

// split x,y into bf16 hi/lo packed pairs
__device__ __forceinline__ void split2(float x, float y, uint32_t& hi, uint32_t& lo) {
    __nv_bfloat16 hx = __float2bfloat16(x);
    __nv_bfloat16 hy = __float2bfloat16(y);
    __nv_bfloat16 lx = __float2bfloat16(x - __bfloat162float(hx));
    __nv_bfloat16 ly = __float2bfloat16(y - __bfloat162float(hy));
    hi = pack_bf2(hx, hy);
    lo = pack_bf2(lx, ly);
}

// ---------------------------------------------------------------------------
// Split-bf16 tensor-core GEMM: C[M=4096, N] = X[4096,1024] @ W[1024,N] + bias
// Tile 128x128, BK=32, 8 warps (2x4), warp tile 64x32.
// A smem: k-major [128][32] bf16, row stride 40 (pad 8) -> ldmatrix.x4 conflict-free.
// B smem: n-major [32][128] bf16, row stride 136 (pad 8) -> ldmatrix.x2.trans.
// MODE 0: qkv (scatter to gQ/gK/gV), MODE 1: proj (write C).
// ---------------------------------------------------------------------------
#define BM 128
#define BN 128
#define BK 32
#define NSTEP (DD/BK)     // 32
#define ASTR 40           // bf16 per A row (80 B)
#define BSTR 136          // bf16 per B row (272 B)

struct SmemGemm {
    __nv_bfloat16 Ahi[BM * ASTR];
    __nv_bfloat16 Alo[BM * ASTR];
    __nv_bfloat16 Bhi[BK * BSTR];
    __nv_bfloat16 Blo[BK * BSTR];
};

template <int MODE>
__global__ __launch_bounds__(256, 1) void mma_gemm_kernel(
    const float* __restrict__ Xp, const float* __restrict__ W,
    const float* __restrict__ bias, float* __restrict__ C)
{
    __shared__ SmemGemm s;
    const int Nn = (MODE == 0) ? N_QKV : DD;
    const float* X = (MODE == 0) ? Xp : gA;
    const int n0 = blockIdx.x * BN;
    const int m0 = blockIdx.y * BM;
    const int tid = threadIdx.x;
    const int lane = tid & 31;
    const int wid = tid >> 5;
    const int wm = wid & 1;       // 0..1 -> rows wm*64
    const int wn = wid >> 1;      // 0..3 -> cols wn*32

    // A loader: one row, one 16-float k-half per thread
    const int arow = tid & 127;
    const int ahalf = tid >> 7;                 // 0 or 1
    const float* aptr = X + (size_t)(m0 + arow) * DD + ahalf * 16;
    // B loader: 4 consecutive k-rows, 4 consecutive n per thread
    const int bg = lane;                        // n-group (4 cols): 0..31
    const int bk0 = (tid >> 5) * 4;             // k rows 0..28
    const float* bptr = W + (size_t)bk0 * Nn + n0 + bg * 4;

    float4 pa[4];
    float4 pb[4];
#pragma unroll
    for (int i = 0; i < 4; i++) pa[i] = __ldg((const float4*)aptr + i);
#pragma unroll
    for (int i = 0; i < 4; i++) pb[i] = __ldg((const float4*)(bptr + (size_t)i * Nn));

    float acc[4][4][4];
#pragma unroll
    for (int mt = 0; mt < 4; mt++)
#pragma unroll
        for (int nt = 0; nt < 4; nt++)
#pragma unroll
            for (int e = 0; e < 4; e++) acc[mt][nt][e] = 0.f;

    const uint32_t sa_hi = smem_u32(s.Ahi);
    const uint32_t sa_lo = smem_u32(s.Alo);
    const uint32_t sb_hi = smem_u32(s.Bhi);
    const uint32_t sb_lo = smem_u32(s.Blo);

    for (int step = 0; step < NSTEP; step++) {
        // ---- convert A (16 floats -> bf16 hi/lo) and store
        {
            const float* pf = (const float*)pa;
            uint32_t hi[8], lo[8];
#pragma unroll
            for (int e = 0; e < 8; e++)
                split2(pf[2 * e], pf[2 * e + 1], hi[e], lo[e]);
            char* dh = (char*)s.Ahi + arow * 80 + ahalf * 32;
            char* dl = (char*)s.Alo + arow * 80 + ahalf * 32;
            *(uint4*)(dh)      = make_uint4(hi[0], hi[1], hi[2], hi[3]);
            *(uint4*)(dh + 16) = make_uint4(hi[4], hi[5], hi[6], hi[7]);
            *(uint4*)(dl)      = make_uint4(lo[0], lo[1], lo[2], lo[3]);
            *(uint4*)(dl + 16) = make_uint4(lo[4], lo[5], lo[6], lo[7]);
        }
        // ---- convert B (4 rows x 4 n) and store (no transpose; n-contiguous)
        {
#pragma unroll
            for (int i = 0; i < 4; i++) {
                uint32_t h0, l0, h1, l1;
                split2(pb[i].x, pb[i].y, h0, l0);
                split2(pb[i].z, pb[i].w, h1, l1);
                char* dh = (char*)s.Bhi + (bk0 + i) * 272 + bg * 8;
                char* dl = (char*)s.Blo + (bk0 + i) * 272 + bg * 8;
                *(uint2*)dh = make_uint2(h0, h1);
                *(uint2*)dl = make_uint2(l0, l1);
            }
        }
        __syncthreads();

        // ---- prefetch next step
        if (step + 1 < NSTEP) {
            const float* a2 = aptr + (size_t)(step + 1) * BK;
            const float* b2 = bptr + (size_t)(step + 1) * BK * Nn;
#pragma unroll
            for (int i = 0; i < 4; i++) pa[i] = __ldg((const float4*)a2 + i);
#pragma unroll
            for (int i = 0; i < 4; i++) pb[i] = __ldg((const float4*)(b2 + (size_t)i * Nn));
        }

        // ---- tensor-core compute on this tile
#pragma unroll
        for (int kk = 0; kk < 2; kk++) {
            const int kb = kk * 16;
            // A fragments: 4 m-tiles, hi + lo
            uint32_t ah[4][4], al[4][4];
            {
                const int r = wm * 64 + (lane & 7) + ((lane >> 3) & 1) * 8;
                const int kc = kb + (lane >> 4) * 8;
#pragma unroll
                for (int mt = 0; mt < 4; mt++) {
                    const uint32_t off = (uint32_t)((r + mt * 16) * 80 + kc * 2);
                    ldm_x4(ah[mt], sa_hi + off);
                    ldm_x4(al[mt], sa_lo + off);
                }
            }
            // B fragments: 4 n-tiles, hi + lo (trans from [k][n])
            uint32_t bh[4][2], bl[4][2];
            {
                const int kr = kb + (lane & 15);
#pragma unroll
                for (int nt = 0; nt < 4; nt++) {
                    const int nc = wn * 32 + nt * 8;
                    const uint32_t off = (uint32_t)(kr * 272 + nc * 2);
                    ldm_x2t(bh[nt], sb_hi + off);
                    ldm_x2t(bl[nt], sb_lo + off);
                }
            }
#pragma unroll
            for (int mt = 0; mt < 4; mt++)
#pragma unroll
                for (int nt = 0; nt < 4; nt++) {
                    mma_bf16(acc[mt][nt], ah[mt], bh[nt]);   // hi*hi
                    mma_bf16(acc[mt][nt], ah[mt], bl[nt]);   // hi*lo
                    mma_bf16(acc[mt][nt], al[mt], bh[nt]);   // lo*hi
                }
        }
        __syncthreads();
    }

    // ---- epilogue: scatter with bias
#pragma unroll
    for (int mt = 0; mt < 4; mt++) {
        const int rbase = m0 + wm * 64 + mt * 16 + (lane >> 2);
#pragma unroll
        for (int nt = 0; nt < 4; nt++) {
            const int col = n0 + wn * 32 + nt * 8 + (lane & 3) * 2;
            const float2 bv = *(const float2*)(bias + col);
#pragma unroll
            for (int rr = 0; rr < 2; rr++) {
                const int m = rbase + rr * 8;
                const float vx = acc[mt][nt][rr * 2 + 0] + bv.x;
                const float vy = acc[mt][nt][rr * 2 + 1] + bv.y;
                float* p;
                if (MODE == 0) {
                    const int which = col >> 10;
                    const int h = (col & (DD - 1)) >> 6;
                    const int dd = col & (DH - 1);
                    const int b = m >> 11, t = m & (TT - 1);
                    float* dst = (which == 0) ? gQ : ((which == 1) ? gK : gV);
                    p = dst + (((size_t)(b * HH + h) * TT) + t) * DH + dd;
                } else {
                    p = C + (size_t)m * DD + col;
                }
                *(float2*)p = make_float2(vx, vy);
            }
        }
    }
}

// ---------------------------------------------------------------------------
// Flash attention (causal), fp32 SIMT. grid = (B*H, T/128), 128 threads.
// (tensor-core port is next round's target)
// ---------------------------------------------------------------------------
__global__ __launch_bounds__(128) void flash_kernel()
{
    const int bh = blockIdx.x;
    const int qtile = blockIdx.y;
    const int tid = threadIdx.x;
    const int qr = qtile * 128 + tid;

    const float4* qptr = (const float4*)(gQ + ((size_t)bh * TT + qr) * DH);
    float4 q[16];
#pragma unroll
    for (int i = 0; i < 16; i++) q[i] = __ldg(qptr + i);

    float acc[64];
#pragma unroll
    for (int d = 0; d < 64; d++) acc[d] = 0.f;
    float m_run = -1e30f, l_run = 0.f;

    __shared__ float4 Ks[64 * 16];
    __shared__ float4 Vs[64 * 16];

    const int ntiles = 2 * qtile + 2;
    for (int tk = 0; tk < ntiles; tk++) {
        const int j0 = tk * 64;
        const float4* kp = (const float4*)(gK + ((size_t)bh * TT + j0) * DH);
        const float4* vp = (const float4*)(gV + ((size_t)bh * TT + j0) * DH);
        __syncthreads();
#pragma unroll
        for (int i = 0; i < 8; i++) {
            Ks[tid + i * 128] = __ldg(kp + tid + i * 128);
            Vs[tid + i * 128] = __ldg(vp + tid + i * 128);
        }
        __syncthreads();

        for (int c = 0; c < 4; c++) {
            const int jb = c * 16;
            if (j0 + jb > qr) break;

            float sc[16];
            float mx = -1e30f;
#pragma unroll
            for (int jj = 0; jj < 16; jj++) {
                const float4* kr = &Ks[(jb + jj) * 16];
                float sv = 0.f;
#pragma unroll
                for (int d4 = 0; d4 < 16; d4++) {
                    float4 kk = kr[d4];
                    sv += q[d4].x * kk.x + q[d4].y * kk.y
                        + q[d4].z * kk.z + q[d4].w * kk.w;
                }
                sv *= 0.125f;
                if (j0 + jb + jj > qr) sv = -1e30f;
                sc[jj] = sv;
                mx = fmaxf(mx, sv);
            }
            const float m_new = fmaxf(m_run, mx);
            const float corr = __expf(m_run - m_new);
            float psum = 0.f;
#pragma unroll
            for (int jj = 0; jj < 16; jj++) {
                sc[jj] = __expf(sc[jj] - m_new);
                psum += sc[jj];
            }
            l_run = l_run * corr + psum;
#pragma unroll
            for (int d = 0; d < 64; d++) acc[d] *= corr;
#pragma unroll
            for (int jj = 0; jj < 16; jj++) {
                const float4* vr = &Vs[(jb + jj) * 16];
                const float p = sc[jj];
#pragma unroll
                for (int d4 = 0; d4 < 16; d4++) {
                    float4 vv = vr[d4];
                    acc[d4 * 4 + 0] += p * vv.x;
                    acc[d4 * 4 + 1] += p * vv.y;
                    acc[d4 * 4 + 2] += p * vv.z;
                    acc[d4 * 4 + 3] += p * vv.w;
                }
            }
            m_run = m_new;
        }
    }

    const float inv = 1.f / l_run;
    const int b = bh >> 4, h = bh & 15;
    float4* op = (float4*)(gA + ((size_t)(b * TT + qr)) * DD + h * DH);
#pragma unroll
    for (int d4 = 0; d4 < 16; d4++) {
        float4 o;
        o.x = acc[d4 * 4 + 0] * inv;
        o.y = acc[d4 * 4 + 1] * inv;
        o.z = acc[d4 * 4 + 2] * inv;
        o.w = acc[d4 * 4 + 3] * inv;
        op[d4] = o;
    }
}

// ---------------------------------------------------------------------------
// Launcher
// ---------------------------------------------------------------------------
extern "C" void kernel_launch(void* const* d_in, const int* in_sizes, int n_in,
                              void* d_out, int out_size)
{
    const float* x      = (const float*)d_in[0];
    const float* W_attn = (const float*)d_in[1];
    const float* b_attn = (const float*)d_in[2];
    const float* W_proj = (const float*)d_in[3];
    const float* b_proj = (const float*)d_in[4];
    float* out = (float*)d_out;

    dim3 g1(N_QKV / BN, MM / BM);       // 24 x 32
    mma_gemm_kernel<0><<<g1, 256>>>(x, W_attn, b_attn, nullptr);

    dim3 g2(BB * HH, TT / 128);         // 32 x 16
    flash_kernel<<<g2, 128>>>();

    dim3 g3(DD / BN, MM / BM);          // 8 x 32
    mma_gemm_kernel<1><<<g3, 256>>>(nullptr, W_proj, b_proj, out);
}

// round 5
// speedup vs baseline: 2.1533x; 2.1533x over previous
#include <cuda_runtime.h>
#include <cuda_bf16.h>
#include <cstdint>

// Problem constants
#define BB 2
#define TT 2048
#define DD 1024
#define HH 16
#define DH 64
#define MM (BB*TT)          // 4096
#define N_QKV (3*DD)        // 3072

// Scratch (device globals — no runtime allocation allowed)
__device__ float gQ[BB*HH*TT*DH];   // [B,H,T,dh]
__device__ float gK[BB*HH*TT*DH];
__device__ float gV[BB*HH*TT*DH];
__device__ float gA[BB*TT*DD];      // merged-head attention output [B,T,D]

// ---------------------------------------------------------------------------
// Helpers (baseline PTX only: ldmatrix + mma.sync)
// ---------------------------------------------------------------------------
__device__ __forceinline__ uint32_t smem_u32(const void* p) {
    uint32_t a;
    asm("{ .reg .u64 t; cvta.to.shared.u64 t, %1; cvt.u32.u64 %0, t; }"
        : "=r"(a) : "l"(p));
    return a;
}

__device__ __forceinline__ void ldm_x4(uint32_t* r, uint32_t addr) {
    asm volatile("ldmatrix.sync.aligned.m8n8.x4.shared.b16 {%0,%1,%2,%3}, [%4];"
                 : "=r"(r[0]), "=r"(r[1]), "=r"(r[2]), "=r"(r[3]) : "r"(addr));
}

__device__ __forceinline__ void ldm_x2(uint32_t* r, uint32_t addr) {
    asm volatile("ldmatrix.sync.aligned.m8n8.x2.shared.b16 {%0,%1}, [%2];"
                 : "=r"(r[0]), "=r"(r[1]) : "r"(addr));
}

__device__ __forceinline__ void ldm_x2t(uint32_t* r, uint32_t addr) {
    asm volatile("ldmatrix.sync.aligned.m8n8.x2.trans.shared.b16 {%0,%1}, [%2];"
                 : "=r"(r[0]), "=r"(r[1]) : "r"(addr));
}

__device__ __forceinline__ void mma_bf16(float* c, const uint32_t* a, const uint32_t* b) {
    asm volatile(
        "mma.sync.aligned.m16n8k16.row.col.f32.bf16.bf16.f32 "
        "{%0,%1,%2,%3}, {%4,%5,%6,%7}, {%8,%9}, {%0,%1,%2,%3};"
        : "+f"(c[0]), "+f"(c[1]), "+f"(c[2]), "+f"(c[3])
        : "r"(a[0]), "r"(a[1]), "r"(a[2]), "r"(a[3]), "r"(b[0]), "r"(b[1]));
}

__device__ __forceinline__ uint32_t pack_bf2(__nv_bfloat16 a, __nv_bfloat16 b) {
    __nv_bfloat162 t(a, b);
    return *reinterpret_cast<uint32_t*>(&t);
}

__device__ __forceinline__ void split2(float x, float y, uint32_t& hi, uint32_t& lo) {
    __nv_bfloat16 hx = __float2bfloat16(x);
    __nv_bfloat16 hy = __float2bfloat16(y);
    __nv_bfloat16 lx = __float2bfloat16(x - __bfloat162float(hx));
    __nv_bfloat16 ly = __float2bfloat16(y - __bfloat162float(hy));
    hi = pack_bf2(hx, hy);
    lo = pack_bf2(lx, ly);
}

// ---------------------------------------------------------------------------
// Split-bf16 tensor-core GEMM (unchanged from R4; passes at rel_err 1e-5)
// ---------------------------------------------------------------------------
#define BM 128
#define BN 128
#define BK 32
#define NSTEP (DD/BK)     // 32
#define ASTR 40
#define BSTR 136

struct SmemGemm {
    __nv_bfloat16 Ahi[BM * ASTR];
    __nv_bfloat16 Alo[BM * ASTR];
    __nv_bfloat16 Bhi[BK * BSTR];
    __nv_bfloat16 Blo[BK * BSTR];
};

template <int MODE>
__global__ __launch_bounds__(256, 1) void mma_gemm_kernel(
    const float* __restrict__ Xp, const float* __restrict__ W,
    const float* __restrict__ bias, float* __restrict__ C)
{
    __shared__ SmemGemm s;
    const int Nn = (MODE == 0) ? N_QKV : DD;
    const float* X = (MODE == 0) ? Xp : gA;
    const int n0 = blockIdx.x * BN;
    const int m0 = blockIdx.y * BM;
    const int tid = threadIdx.x;
    const int lane = tid & 31;
    const int wid = tid >> 5;
    const int wm = wid & 1;
    const int wn = wid >> 1;

    const int arow = tid & 127;
    const int ahalf = tid >> 7;
    const float* aptr = X + (size_t)(m0 + arow) * DD + ahalf * 16;
    const int bg = lane;
    const int bk0 = (tid >> 5) * 4;
    const float* bptr = W + (size_t)bk0 * Nn + n0 + bg * 4;

    float4 pa[4];
    float4 pb[4];
#pragma unroll
    for (int i = 0; i < 4; i++) pa[i] = __ldg((const float4*)aptr + i);
#pragma unroll
    for (int i = 0; i < 4; i++) pb[i] = __ldg((const float4*)(bptr + (size_t)i * Nn));

    float acc[4][4][4];
#pragma unroll
    for (int mt = 0; mt < 4; mt++)
#pragma unroll
        for (int nt = 0; nt < 4; nt++)
#pragma unroll
            for (int e = 0; e < 4; e++) acc[mt][nt][e] = 0.f;

    const uint32_t sa_hi = smem_u32(s.Ahi);
    const uint32_t sa_lo = smem_u32(s.Alo);
    const uint32_t sb_hi = smem_u32(s.Bhi);
    const uint32_t sb_lo = smem_u32(s.Blo);

    for (int step = 0; step < NSTEP; step++) {
        {
            const float* pf = (const float*)pa;
            uint32_t hi[8], lo[8];
#pragma unroll
            for (int e = 0; e < 8; e++)
                split2(pf[2 * e], pf[2 * e + 1], hi[e], lo[e]);
            char* dh = (char*)s.Ahi + arow * 80 + ahalf * 32;
            char* dl = (char*)s.Alo + arow * 80 + ahalf * 32;
            *(uint4*)(dh)      = make_uint4(hi[0], hi[1], hi[2], hi[3]);
            *(uint4*)(dh + 16) = make_uint4(hi[4], hi[5], hi[6], hi[7]);
            *(uint4*)(dl)      = make_uint4(lo[0], lo[1], lo[2], lo[3]);
            *(uint4*)(dl + 16) = make_uint4(lo[4], lo[5], lo[6], lo[7]);
        }
        {
#pragma unroll
            for (int i = 0; i < 4; i++) {
                uint32_t h0, l0, h1, l1;
                split2(pb[i].x, pb[i].y, h0, l0);
                split2(pb[i].z, pb[i].w, h1, l1);
                char* dh = (char*)s.Bhi + (bk0 + i) * 272 + bg * 8;
                char* dl = (char*)s.Blo + (bk0 + i) * 272 + bg * 8;
                *(uint2*)dh = make_uint2(h0, h1);
                *(uint2*)dl = make_uint2(l0, l1);
            }
        }
        __syncthreads();

        if (step + 1 < NSTEP) {
            const float* a2 = aptr + (size_t)(step + 1) * BK;
            const float* b2 = bptr + (size_t)(step + 1) * BK * Nn;
#pragma unroll
            for (int i = 0; i < 4; i++) pa[i] = __ldg((const float4*)a2 + i);
#pragma unroll
            for (int i = 0; i < 4; i++) pb[i] = __ldg((const float4*)(b2 + (size_t)i * Nn));
        }

#pragma unroll
        for (int kk = 0; kk < 2; kk++) {
            const int kb = kk * 16;
            uint32_t ah[4][4], al[4][4];
            {
                const int r = wm * 64 + (lane & 7) + ((lane >> 3) & 1) * 8;
                const int kc = kb + (lane >> 4) * 8;
#pragma unroll
                for (int mt = 0; mt < 4; mt++) {
                    const uint32_t off = (uint32_t)((r + mt * 16) * 80 + kc * 2);
                    ldm_x4(ah[mt], sa_hi + off);
                    ldm_x4(al[mt], sa_lo + off);
                }
            }
            uint32_t bh[4][2], bl[4][2];
            {
                const int kr = kb + (lane & 15);
#pragma unroll
                for (int nt = 0; nt < 4; nt++) {
                    const int nc = wn * 32 + nt * 8;
                    const uint32_t off = (uint32_t)(kr * 272 + nc * 2);
                    ldm_x2t(bh[nt], sb_hi + off);
                    ldm_x2t(bl[nt], sb_lo + off);
                }
            }
#pragma unroll
            for (int mt = 0; mt < 4; mt++)
#pragma unroll
                for (int nt = 0; nt < 4; nt++) {
                    mma_bf16(acc[mt][nt], ah[mt], bh[nt]);
                    mma_bf16(acc[mt][nt], ah[mt], bl[nt]);
                    mma_bf16(acc[mt][nt], al[mt], bh[nt]);
                }
        }
        __syncthreads();
    }

#pragma unroll
    for (int mt = 0; mt < 4; mt++) {
        const int rbase = m0 + wm * 64 + mt * 16 + (lane >> 2);
#pragma unroll
        for (int nt = 0; nt < 4; nt++) {
            const int col = n0 + wn * 32 + nt * 8 + (lane & 3) * 2;
            const float2 bv = *(const float2*)(bias + col);
#pragma unroll
            for (int rr = 0; rr < 2; rr++) {
                const int m = rbase + rr * 8;
                const float vx = acc[mt][nt][rr * 2 + 0] + bv.x;
                const float vy = acc[mt][nt][rr * 2 + 1] + bv.y;
                float* p;
                if (MODE == 0) {
                    const int which = col >> 10;
                    const int h = (col & (DD - 1)) >> 6;
                    const int dd = col & (DH - 1);
                    const int b = m >> 11, t = m & (TT - 1);
                    float* dst = (which == 0) ? gQ : ((which == 1) ? gK : gV);
                    p = dst + (((size_t)(b * HH + h) * TT) + t) * DH + dd;
                } else {
                    p = C + (size_t)m * DD + col;
                }
                *(float2*)p = make_float2(vx, vy);
            }
        }
    }
}

// ---------------------------------------------------------------------------
// Tensor-core flash attention (causal). Block = 64 q-rows of one head.
// 4 warps x 16 rows. grid = (B*H, T/64), largest q-tiles scheduled first.
// Split-bf16 for both Q*K^T (3 MMAs) and P*V (3 MMAs). fp32 softmax in regs.
// ---------------------------------------------------------------------------
#define FSTR 72   // bf16 per smem row (144 B), pad 8

struct SmemFlash {
    __nv_bfloat16 Khi[64 * FSTR];   // also Q-hi staging before main loop
    __nv_bfloat16 Klo[64 * FSTR];   // also Q-lo staging
    __nv_bfloat16 Vhi[64 * FSTR];
    __nv_bfloat16 Vlo[64 * FSTR];
};

__global__ __launch_bounds__(128) void flash_tc_kernel()
{
    __shared__ SmemFlash s;
    const int bh = blockIdx.x;                      // head
    const int qt = gridDim.y - 1 - blockIdx.y;      // big tiles first
    const int q0 = qt * 64;
    const int tid = threadIdx.x;
    const int lane = tid & 31;
    const int wq = tid >> 5;                        // warp -> rows wq*16

    const uint32_t sKh = smem_u32(s.Khi);
    const uint32_t sKl = smem_u32(s.Klo);
    const uint32_t sVh = smem_u32(s.Vhi);
    const uint32_t sVl = smem_u32(s.Vlo);

    const size_t headoff = (size_t)bh * TT * DH;

    // ---- stage Q (scaled by 1/8, split) into K buffers, then to register frags
    {
        const int r = tid >> 1;
        const int ch = (tid & 1) * 32;
        const float* qp = gQ + headoff + (size_t)(q0 + r) * DH + ch;
        float4 f[8];
#pragma unroll
        for (int i = 0; i < 8; i++) f[i] = __ldg((const float4*)qp + i);
        const float* pf = (const float*)f;
        char* dh = (char*)s.Khi + r * 144 + ch * 2;
        char* dl = (char*)s.Klo + r * 144 + ch * 2;
#pragma unroll
        for (int j = 0; j < 4; j++) {
            uint32_t hi[4], lo[4];
#pragma unroll
            for (int e = 0; e < 4; e++)
                split2(pf[j * 8 + 2 * e] * 0.125f, pf[j * 8 + 2 * e + 1] * 0.125f,
                       hi[e], lo[e]);
            *(uint4*)(dh + j * 16) = make_uint4(hi[0], hi[1], hi[2], hi[3]);
            *(uint4*)(dl + j * 16) = make_uint4(lo[0], lo[1], lo[2], lo[3]);
        }
    }
    __syncthreads();

    uint32_t qh[4][4], ql[4][4];
    {
        const int r = wq * 16 + (lane & 7) + ((lane >> 3) & 1) * 8;
#pragma unroll
        for (int ks = 0; ks < 4; ks++) {
            const int kc = ks * 16 + (lane >> 4) * 8;
            const uint32_t off = (uint32_t)(r * 144 + kc * 2);
            ldm_x4(qh[ks], sKh + off);
            ldm_x4(ql[ks], sKl + off);
        }
    }
    __syncthreads();   // all warps done reading staging

    // softmax / output state
    float o[8][4];
#pragma unroll
    for (int nt = 0; nt < 8; nt++)
#pragma unroll
        for (int e = 0; e < 4; e++) o[nt][e] = 0.f;
    float m0r = -1e30f, m1r = -1e30f, l0r = 0.f, l1r = 0.f;

    const int row0 = wq * 16 + (lane >> 2);   // local q row (and +8)

    for (int jt = 0; jt <= qt; jt++) {
        const int j0 = jt * 64;

        // ---- issue K/V global loads (overlap with previous compute)
        const int kr = tid >> 1;
        const int ch = (tid & 1) * 32;
        const float* kp = gK + headoff + (size_t)(j0 + kr) * DH + ch;
        const float* vp = gV + headoff + (size_t)(j0 + kr) * DH + ch;
        float4 fk[8], fv[8];
#pragma unroll
        for (int i = 0; i < 8; i++) fk[i] = __ldg((const float4*)kp + i);
#pragma unroll
        for (int i = 0; i < 8; i++) fv[i] = __ldg((const float4*)vp + i);

        __syncthreads();   // previous compute finished reading smem

        {
            const float* pk = (const float*)fk;
            const float* pv = (const float*)fv;
            char* dkh = (char*)s.Khi + kr * 144 + ch * 2;
            char* dkl = (char*)s.Klo + kr * 144 + ch * 2;
            char* dvh = (char*)s.Vhi + kr * 144 + ch * 2;
            char* dvl = (char*)s.Vlo + kr * 144 + ch * 2;
#pragma unroll
            for (int j = 0; j < 4; j++) {
                uint32_t hi[4], lo[4];
#pragma unroll
                for (int e = 0; e < 4; e++)
                    split2(pk[j * 8 + 2 * e], pk[j * 8 + 2 * e + 1], hi[e], lo[e]);
                *(uint4*)(dkh + j * 16) = make_uint4(hi[0], hi[1], hi[2], hi[3]);
                *(uint4*)(dkl + j * 16) = make_uint4(lo[0], lo[1], lo[2], lo[3]);
#pragma unroll
                for (int e = 0; e < 4; e++)
                    split2(pv[j * 8 + 2 * e], pv[j * 8 + 2 * e + 1], hi[e], lo[e]);
                *(uint4*)(dvh + j * 16) = make_uint4(hi[0], hi[1], hi[2], hi[3]);
                *(uint4*)(dvl + j * 16) = make_uint4(lo[0], lo[1], lo[2], lo[3]);
            }
        }
        __syncthreads();

        // ---- S = Q K^T (split-bf16)
        float sc[8][4];
#pragma unroll
        for (int nt = 0; nt < 8; nt++)
#pragma unroll
            for (int e = 0; e < 4; e++) sc[nt][e] = 0.f;

#pragma unroll
        for (int ks = 0; ks < 4; ks++) {
            uint32_t bh2[8][2], bl2[8][2];
            const int ln = lane & 15;
#pragma unroll
            for (int nt = 0; nt < 8; nt++) {
                const uint32_t off =
                    (uint32_t)((nt * 8 + (ln & 7)) * 144 + ks * 32 + ((ln >> 3) & 1) * 16);
                ldm_x2(bh2[nt], sKh + off);
                ldm_x2(bl2[nt], sKl + off);
            }
#pragma unroll
            for (int nt = 0; nt < 8; nt++) {
                mma_bf16(sc[nt], qh[ks], bh2[nt]);
                mma_bf16(sc[nt], qh[ks], bl2[nt]);
                mma_bf16(sc[nt], ql[ks], bh2[nt]);
            }
        }

        // ---- causal mask on diagonal tile
        if (jt == qt) {
            const int cbase = (lane & 3) * 2;
#pragma unroll
            for (int nt = 0; nt < 8; nt++) {
                const int c0 = nt * 8 + cbase;
                if (c0 > row0)     sc[nt][0] = -1e30f;
                if (c0 + 1 > row0) sc[nt][1] = -1e30f;
                if (c0 > row0 + 8)     sc[nt][2] = -1e30f;
                if (c0 + 1 > row0 + 8) sc[nt][3] = -1e30f;
            }
        }

        // ---- online softmax (rows row0, row0+8)
        float mx0 = -1e30f, mx1 = -1e30f;
#pragma unroll
        for (int nt = 0; nt < 8; nt++) {
            mx0 = fmaxf(mx0, fmaxf(sc[nt][0], sc[nt][1]));
            mx1 = fmaxf(mx1, fmaxf(sc[nt][2], sc[nt][3]));
        }
        mx0 = fmaxf(mx0, __shfl_xor_sync(0xffffffffu, mx0, 1));
        mx0 = fmaxf(mx0, __shfl_xor_sync(0xffffffffu, mx0, 2));
        mx1 = fmaxf(mx1, __shfl_xor_sync(0xffffffffu, mx1, 1));
        mx1 = fmaxf(mx1, __shfl_xor_sync(0xffffffffu, mx1, 2));

        const float mn0 = fmaxf(m0r, mx0);
        const float mn1 = fmaxf(m1r, mx1);
        const float c0 = __expf(m0r - mn0);
        const float c1 = __expf(m1r - mn1);

        float sum0 = 0.f, sum1 = 0.f;
#pragma unroll
        for (int nt = 0; nt < 8; nt++) {
            sc[nt][0] = __expf(sc[nt][0] - mn0);
            sc[nt][1] = __expf(sc[nt][1] - mn0);
            sc[nt][2] = __expf(sc[nt][2] - mn1);
            sc[nt][3] = __expf(sc[nt][3] - mn1);
            sum0 += sc[nt][0] + sc[nt][1];
            sum1 += sc[nt][2] + sc[nt][3];
        }
        sum0 += __shfl_xor_sync(0xffffffffu, sum0, 1);
        sum0 += __shfl_xor_sync(0xffffffffu, sum0, 2);
        sum1 += __shfl_xor_sync(0xffffffffu, sum1, 1);
        sum1 += __shfl_xor_sync(0xffffffffu, sum1, 2);

        l0r = l0r * c0 + sum0;
        l1r = l1r * c1 + sum1;
        m0r = mn0;
        m1r = mn1;

#pragma unroll
        for (int nt = 0; nt < 8; nt++) {
            o[nt][0] *= c0; o[nt][1] *= c0;
            o[nt][2] *= c1; o[nt][3] *= c1;
        }

        // ---- P V (split P x split V)
#pragma unroll
        for (int ks = 0; ks < 4; ks++) {
            // pack P fragments from score tiles 2ks, 2ks+1
            uint32_t ph[4], pl[4];
            split2(sc[2 * ks][0],     sc[2 * ks][1],     ph[0], pl[0]);
            split2(sc[2 * ks][2],     sc[2 * ks][3],     ph[1], pl[1]);
            split2(sc[2 * ks + 1][0], sc[2 * ks + 1][1], ph[2], pl[2]);
            split2(sc[2 * ks + 1][2], sc[2 * ks + 1][3], ph[3], pl[3]);

            const int krr = ks * 16 + (lane & 15);
#pragma unroll
            for (int nt = 0; nt < 8; nt++) {
                uint32_t vh[2], vl[2];
                const uint32_t off = (uint32_t)(krr * 144 + nt * 16);
                ldm_x2t(vh, sVh + off);
                ldm_x2t(vl, sVl + off);
                mma_bf16(o[nt], ph, vh);
                mma_bf16(o[nt], ph, vl);
                mma_bf16(o[nt], pl, vh);
            }
        }
    }

    // ---- epilogue: write gA[b, t, h*64 + col]
    const float inv0 = 1.f / l0r;
    const float inv1 = 1.f / l1r;
    const int b = bh >> 4, h = bh & 15;
    const int t0 = q0 + row0;
#pragma unroll
    for (int nt = 0; nt < 8; nt++) {
        const int col = h * DH + nt * 8 + (lane & 3) * 2;
        float* p0 = gA + ((size_t)(b * TT + t0)) * DD + col;
        float* p1 = gA + ((size_t)(b * TT + t0 + 8)) * DD + col;
        *(float2*)p0 = make_float2(o[nt][0] * inv0, o[nt][1] * inv0);
        *(float2*)p1 = make_float2(o[nt][2] * inv1, o[nt][3] * inv1);
    }
}

// ---------------------------------------------------------------------------
// Launcher
// ---------------------------------------------------------------------------
extern "C" void kernel_launch(void* const* d_in, const int* in_sizes, int n_in,
                              void* d_out, int out_size)
{
    const float* x      = (const float*)d_in[0];
    const float* W_attn = (const float*)d_in[1];
    const float* b_attn = (const float*)d_in[2];
    const float* W_proj = (const float*)d_in[3];
    const float* b_proj = (const float*)d_in[4];
    float* out = (float*)d_out;

    dim3 g1(N_QKV / BN, MM / BM);       // 24 x 32
    mma_gemm_kernel<0><<<g1, 256>>>(x, W_attn, b_attn, nullptr);

    dim3 g2(BB * HH, TT / 64);          // 32 x 32
    flash_tc_kernel<<<g2, 128>>>();

    dim3 g3(DD / BN, MM / BM);          // 8 x 32
    mma_gemm_kernel<1><<<g3, 256>>>(nullptr, W_proj, b_proj, out);
}

// round 6
// speedup vs baseline: 4.0300x; 1.8716x over previous
#include <cuda_runtime.h>
#include <cuda_bf16.h>
#include <cstdint>

// Problem constants
#define BB 2
#define TT 2048
#define DD 1024
#define HH 16
#define DH 64
#define MM (BB*TT)          // 4096
#define N_QKV (3*DD)        // 3072

// ---------------------------------------------------------------------------
// Persistent split-bf16 scratch (device globals — no runtime allocation)
// ---------------------------------------------------------------------------
__device__ __align__(16) __nv_bfloat16 Xh[MM*DD],  Xl[MM*DD];
__device__ __align__(16) __nv_bfloat16 Wah[DD*N_QKV], Wal[DD*N_QKV];
__device__ __align__(16) __nv_bfloat16 Wph[DD*DD], Wpl[DD*DD];
__device__ __align__(16) __nv_bfloat16 gQh[BB*HH*TT*DH], gQl[BB*HH*TT*DH];
__device__ __align__(16) __nv_bfloat16 gKh[BB*HH*TT*DH], gKl[BB*HH*TT*DH];
__device__ __align__(16) __nv_bfloat16 gVh[BB*HH*TT*DH], gVl[BB*HH*TT*DH];
__device__ __align__(16) __nv_bfloat16 gAh[MM*DD], gAl[MM*DD];

// ---------------------------------------------------------------------------
// Helpers (baseline PTX: ldmatrix, mma.sync, cp.async — all sm_80)
// ---------------------------------------------------------------------------
__device__ __forceinline__ uint32_t smem_u32(const void* p) {
    uint32_t a;
    asm("{ .reg .u64 t; cvta.to.shared.u64 t, %1; cvt.u32.u64 %0, t; }"
        : "=r"(a) : "l"(p));
    return a;
}

__device__ __forceinline__ void ldm_x4(uint32_t* r, uint32_t addr) {
    asm volatile("ldmatrix.sync.aligned.m8n8.x4.shared.b16 {%0,%1,%2,%3}, [%4];"
                 : "=r"(r[0]), "=r"(r[1]), "=r"(r[2]), "=r"(r[3]) : "r"(addr));
}
__device__ __forceinline__ void ldm_x2(uint32_t* r, uint32_t addr) {
    asm volatile("ldmatrix.sync.aligned.m8n8.x2.shared.b16 {%0,%1}, [%2];"
                 : "=r"(r[0]), "=r"(r[1]) : "r"(addr));
}
__device__ __forceinline__ void ldm_x2t(uint32_t* r, uint32_t addr) {
    asm volatile("ldmatrix.sync.aligned.m8n8.x2.trans.shared.b16 {%0,%1}, [%2];"
                 : "=r"(r[0]), "=r"(r[1]) : "r"(addr));
}
__device__ __forceinline__ void mma_bf16(float* c, const uint32_t* a, const uint32_t* b) {
    asm volatile(
        "mma.sync.aligned.m16n8k16.row.col.f32.bf16.bf16.f32 "
        "{%0,%1,%2,%3}, {%4,%5,%6,%7}, {%8,%9}, {%0,%1,%2,%3};"
        : "+f"(c[0]), "+f"(c[1]), "+f"(c[2]), "+f"(c[3])
        : "r"(a[0]), "r"(a[1]), "r"(a[2]), "r"(a[3]), "r"(b[0]), "r"(b[1]));
}
__device__ __forceinline__ uint32_t pack_bf2(__nv_bfloat16 a, __nv_bfloat16 b) {
    __nv_bfloat162 t(a, b);
    return *reinterpret_cast<uint32_t*>(&t);
}
__device__ __forceinline__ void split2(float x, float y, uint32_t& hi, uint32_t& lo) {
    __nv_bfloat16 hx = __float2bfloat16(x);
    __nv_bfloat16 hy = __float2bfloat16(y);
    __nv_bfloat16 lx = __float2bfloat16(x - __bfloat162float(hx));
    __nv_bfloat16 ly = __float2bfloat16(y - __bfloat162float(hy));
    hi = pack_bf2(hx, hy);
    lo = pack_bf2(lx, ly);
}
__device__ __forceinline__ void cp16(uint32_t dst, const void* src) {
    asm volatile("cp.async.cg.shared.global [%0], [%1], 16;"
                 :: "r"(dst), "l"(src) : "memory");
}
#define CP_COMMIT() asm volatile("cp.async.commit_group;" ::: "memory")
#define CP_WAIT1()  asm volatile("cp.async.wait_group 1;" ::: "memory")
#define CP_WAIT0()  asm volatile("cp.async.wait_group 0;" ::: "memory")

// ---------------------------------------------------------------------------
// Prep: f32 -> bf16 hi/lo split (vectorized)
// WHICH: 0 = x -> Xh/Xl, 1 = W_attn -> Wah/Wal, 2 = W_proj -> Wph/Wpl
// ---------------------------------------------------------------------------
template <int WHICH>
__global__ void prep_split(const float4* __restrict__ in, int n4)
{
    __nv_bfloat16* oh = (WHICH == 0) ? Xh : ((WHICH == 1) ? Wah : Wph);
    __nv_bfloat16* ol = (WHICH == 0) ? Xl : ((WHICH == 1) ? Wal : Wpl);
    const int i = blockIdx.x * blockDim.x + threadIdx.x;
    if (i < n4) {
        float4 v = __ldg(in + i);
        uint32_t h0, l0, h1, l1;
        split2(v.x, v.y, h0, l0);
        split2(v.z, v.w, h1, l1);
        ((uint2*)oh)[i] = make_uint2(h0, h1);
        ((uint2*)ol)[i] = make_uint2(l0, l1);
    }
}

// ---------------------------------------------------------------------------
// Pipelined split-bf16 tensor-core GEMM. Tile 128x128, BK=64, 2-stage cp.async.
// smem per stage: Ah 16K | Al 16K | Bh 16K | Bl 16K = 64KB; 2 stages = 128KB.
// A rows 128B (8 chunks, swizzle c^(r&7)); B rows 256B (16 chunks, low-3 XOR).
// MODE 0: qkv from Xh/Xl x Wah/Wal -> split-bf16 Q(scaled)/K/V.
// MODE 1: proj from gAh/gAl x Wph/Wpl -> f32 C.
// ---------------------------------------------------------------------------
#define BM 128
#define BN 128
#define GSTG 65536

template <int MODE>
__global__ __launch_bounds__(256, 1) void gemm2(
    const float* __restrict__ bias, float* __restrict__ C)
{
    extern __shared__ char smem[];
    const uint32_t sbase = smem_u32(smem);
    const __nv_bfloat16* Ah = (MODE == 0) ? Xh : gAh;
    const __nv_bfloat16* Al = (MODE == 0) ? Xl : gAl;
    const __nv_bfloat16* Bh = (MODE == 0) ? Wah : Wph;
    const __nv_bfloat16* Bl = (MODE == 0) ? Wal : Wpl;
    const int Nn = (MODE == 0) ? N_QKV : DD;
    const int n0 = blockIdx.x * BN;
    const int m0 = blockIdx.y * BM;
    const int tid = threadIdx.x;
    const int lane = tid & 31;
    const int wid = tid >> 5;
    const int wm = wid & 1;
    const int wn = wid >> 1;

    auto issue = [&](int step) {
        const uint32_t sb = sbase + (step & 1) * GSTG;
        const int k0 = step * 64;
        {   // A tile: 128 rows x 64 bf16 (hi + lo)
            const int r = tid >> 1, cb = (tid & 1) * 4;
            const __nv_bfloat16* sh = Ah + (size_t)(m0 + r) * DD + k0 + cb * 8;
            const __nv_bfloat16* sl = Al + (size_t)(m0 + r) * DD + k0 + cb * 8;
            const uint32_t db = sb + r * 128;
#pragma unroll
            for (int i = 0; i < 4; i++) {
                const int c = cb + i;
                const uint32_t sw = (uint32_t)(((c ^ r) & 7) * 16);
                cp16(db + sw, sh + i * 8);
                cp16(db + 16384 + sw, sl + i * 8);
            }
        }
        {   // B tile: 64 rows x 128 bf16 (hi + lo)
            const int r = tid >> 2, cb = (tid & 3) * 4;
            const __nv_bfloat16* sh = Bh + (size_t)(k0 + r) * Nn + n0 + cb * 8;
            const __nv_bfloat16* sl = Bl + (size_t)(k0 + r) * Nn + n0 + cb * 8;
            const uint32_t db = sb + 32768 + r * 256;
#pragma unroll
            for (int i = 0; i < 4; i++) {
                const int c = cb + i;
                const uint32_t sw = (uint32_t)((((c & 8) | ((c ^ r) & 7))) * 16);
                cp16(db + sw, sh + i * 8);
                cp16(db + 16384 + sw, sl + i * 8);
            }
        }
    };

    float acc[4][4][4];
#pragma unroll
    for (int mt = 0; mt < 4; mt++)
#pragma unroll
        for (int nt = 0; nt < 4; nt++)
#pragma unroll
            for (int e = 0; e < 4; e++) acc[mt][nt][e] = 0.f;

    issue(0); CP_COMMIT();

    for (int step = 0; step < 16; step++) {
        if (step + 1 < 16) { issue(step + 1); CP_COMMIT(); CP_WAIT1(); }
        else               { CP_WAIT0(); }
        __syncthreads();

        const uint32_t sb = sbase + (step & 1) * GSTG;
#pragma unroll
        for (int kk = 0; kk < 4; kk++) {
            uint32_t ah[4][4], al[4][4];
            const int rb = wm * 64 + (lane & 7) + ((lane >> 3) & 1) * 8;
            const int ch = kk * 2 + (lane >> 4);
#pragma unroll
            for (int mt = 0; mt < 4; mt++) {
                const int r = rb + mt * 16;
                const uint32_t off = (uint32_t)(r * 128 + ((ch ^ r) & 7) * 16);
                ldm_x4(ah[mt], sb + off);
                ldm_x4(al[mt], sb + 16384 + off);
            }
            uint32_t bh[4][2], bl[4][2];
            const int kr = kk * 16 + (lane & 15);
#pragma unroll
            for (int nt = 0; nt < 4; nt++) {
                const int cB = wn * 4 + nt;
                const uint32_t off =
                    (uint32_t)(kr * 256 + ((cB & 8) | ((cB ^ kr) & 7)) * 16);
                ldm_x2t(bh[nt], sb + 32768 + off);
                ldm_x2t(bl[nt], sb + 49152 + off);
            }
#pragma unroll
            for (int mt = 0; mt < 4; mt++)
#pragma unroll
                for (int nt = 0; nt < 4; nt++) {
                    mma_bf16(acc[mt][nt], ah[mt], bh[nt]);
                    mma_bf16(acc[mt][nt], ah[mt], bl[nt]);
                    mma_bf16(acc[mt][nt], al[mt], bh[nt]);
                }
        }
        __syncthreads();
    }

    // epilogue
#pragma unroll
    for (int mt = 0; mt < 4; mt++) {
        const int rb = m0 + wm * 64 + mt * 16 + (lane >> 2);
#pragma unroll
        for (int nt = 0; nt < 4; nt++) {
            const int col = n0 + wn * 32 + nt * 8 + (lane & 3) * 2;
            const float2 bv = *(const float2*)(bias + col);
#pragma unroll
            for (int rr = 0; rr < 2; rr++) {
                const int m = rb + rr * 8;
                float vx = acc[mt][nt][rr * 2 + 0] + bv.x;
                float vy = acc[mt][nt][rr * 2 + 1] + bv.y;
                if (MODE == 0) {
                    const int which = col >> 10;
                    if (which == 0) { vx *= 0.125f; vy *= 0.125f; }   // Q pre-scale
                    const int h = (col & (DD - 1)) >> 6;
                    const int dd = col & (DH - 1);
                    const int b = m >> 11, t = m & (TT - 1);
                    const size_t idx = (((size_t)(b * HH + h) * TT) + t) * DH + dd;
                    uint32_t hi, lo;
                    split2(vx, vy, hi, lo);
                    __nv_bfloat16 *dh, *dl;
                    if (which == 0)      { dh = gQh; dl = gQl; }
                    else if (which == 1) { dh = gKh; dl = gKl; }
                    else                 { dh = gVh; dl = gVl; }
                    *(uint32_t*)(dh + idx) = hi;
                    *(uint32_t*)(dl + idx) = lo;
                } else {
                    *(float2*)(C + (size_t)m * DD + col) = make_float2(vx, vy);
                }
            }
        }
    }
}

// ---------------------------------------------------------------------------
// Tensor-core flash attention on pre-split bf16 Q/K/V. Block = 64 q-rows.
// smem: Qh 8K | Ql 8K | 2 stages x (Kh 8K | Kl 8K | Vh 8K | Vl 8K) = 80KB.
// ---------------------------------------------------------------------------
#define FSTG 32768

__global__ __launch_bounds__(128) void flash2()
{
    extern __shared__ char smem[];
    const uint32_t sbase = smem_u32(smem);
    const int bh = blockIdx.x;
    const int qt = gridDim.y - 1 - blockIdx.y;      // big tiles first
    const int q0 = qt * 64;
    const int tid = threadIdx.x;
    const int lane = tid & 31;
    const int wq = tid >> 5;
    const size_t hoff = (size_t)bh * TT * DH;

    // ---- issue Q (hi/lo) into staging
    {
        const int r = tid >> 1, cb = (tid & 1) * 4;
        const size_t go = hoff + (size_t)(q0 + r) * DH + cb * 8;
        const uint32_t db = sbase + r * 128;
#pragma unroll
        for (int i = 0; i < 4; i++) {
            const int c = cb + i;
            const uint32_t sw = (uint32_t)(((c ^ r) & 7) * 16);
            cp16(db + sw, gQh + go + i * 8);
            cp16(db + 8192 + sw, gQl + go + i * 8);
        }
    }
    CP_COMMIT();

    auto issueKV = [&](int jt) {
        const uint32_t db0 = sbase + 16384 + (jt & 1) * FSTG;
        const int j0 = jt * 64;
        const int r = tid >> 1, cb = (tid & 1) * 4;
        const size_t go = hoff + (size_t)(j0 + r) * DH + cb * 8;
        const uint32_t db = db0 + r * 128;
#pragma unroll
        for (int i = 0; i < 4; i++) {
            const int c = cb + i;
            const uint32_t sw = (uint32_t)(((c ^ r) & 7) * 16);
            cp16(db + sw,         gKh + go + i * 8);
            cp16(db + 8192 + sw,  gKl + go + i * 8);
            cp16(db + 16384 + sw, gVh + go + i * 8);
            cp16(db + 24576 + sw, gVl + go + i * 8);
        }
    };

    issueKV(0); CP_COMMIT();
    CP_WAIT1(); __syncthreads();

    // Q fragments (pre-scaled by 1/8 at creation)
    uint32_t qh[4][4], ql[4][4];
    {
        const int r = wq * 16 + (lane & 7) + ((lane >> 3) & 1) * 8;
#pragma unroll
        for (int ks = 0; ks < 4; ks++) {
            const int ch = ks * 2 + (lane >> 4);
            const uint32_t off = (uint32_t)(r * 128 + ((ch ^ r) & 7) * 16);
            ldm_x4(qh[ks], sbase + off);
            ldm_x4(ql[ks], sbase + 8192 + off);
        }
    }

    float o[8][4];
#pragma unroll
    for (int nt = 0; nt < 8; nt++)
#pragma unroll
        for (int e = 0; e < 4; e++) o[nt][e] = 0.f;
    float m0r = -1e30f, m1r = -1e30f, l0r = 0.f, l1r = 0.f;
    const int row0 = wq * 16 + (lane >> 2);

    for (int jt = 0; jt <= qt; jt++) {
        if (jt + 1 <= qt) { issueKV(jt + 1); CP_COMMIT(); CP_WAIT1(); }
        else              { CP_WAIT0(); }
        __syncthreads();

        const uint32_t kb = sbase + 16384 + (jt & 1) * FSTG;
        const uint32_t vb = kb + 16384;

        // ---- S = Q K^T
        float sc[8][4];
#pragma unroll
        for (int nt = 0; nt < 8; nt++)
#pragma unroll
            for (int e = 0; e < 4; e++) sc[nt][e] = 0.f;

#pragma unroll
        for (int ks = 0; ks < 4; ks++) {
            uint32_t bh2[8][2], bl2[8][2];
            const int ln = lane & 15;
            const int ch = ks * 2 + ((ln >> 3) & 1);
#pragma unroll
            for (int nt = 0; nt < 8; nt++) {
                const int r = nt * 8 + (ln & 7);
                const uint32_t off = (uint32_t)(r * 128 + ((ch ^ r) & 7) * 16);
                ldm_x2(bh2[nt], kb + off);
                ldm_x2(bl2[nt], kb + 8192 + off);
            }
#pragma unroll
            for (int nt = 0; nt < 8; nt++) {
                mma_bf16(sc[nt], qh[ks], bh2[nt]);
                mma_bf16(sc[nt], qh[ks], bl2[nt]);
                mma_bf16(sc[nt], ql[ks], bh2[nt]);
            }
        }

        // ---- causal mask on diagonal tile
        if (jt == qt) {
            const int cbase = (lane & 3) * 2;
#pragma unroll
            for (int nt = 0; nt < 8; nt++) {
                const int c0 = nt * 8 + cbase;
                if (c0 > row0)         sc[nt][0] = -1e30f;
                if (c0 + 1 > row0)     sc[nt][1] = -1e30f;
                if (c0 > row0 + 8)     sc[nt][2] = -1e30f;
                if (c0 + 1 > row0 + 8) sc[nt][3] = -1e30f;
            }
        }

        // ---- online softmax
        float mx0 = -1e30f, mx1 = -1e30f;
#pragma unroll
        for (int nt = 0; nt < 8; nt++) {
            mx0 = fmaxf(mx0, fmaxf(sc[nt][0], sc[nt][1]));
            mx1 = fmaxf(mx1, fmaxf(sc[nt][2], sc[nt][3]));
        }
        mx0 = fmaxf(mx0, __shfl_xor_sync(0xffffffffu, mx0, 1));
        mx0 = fmaxf(mx0, __shfl_xor_sync(0xffffffffu, mx0, 2));
        mx1 = fmaxf(mx1, __shfl_xor_sync(0xffffffffu, mx1, 1));
        mx1 = fmaxf(mx1, __shfl_xor_sync(0xffffffffu, mx1, 2));

        const float mn0 = fmaxf(m0r, mx0);
        const float mn1 = fmaxf(m1r, mx1);
        const float c0 = __expf(m0r - mn0);
        const float c1 = __expf(m1r - mn1);

        float sum0 = 0.f, sum1 = 0.f;
#pragma unroll
        for (int nt = 0; nt < 8; nt++) {
            sc[nt][0] = __expf(sc[nt][0] - mn0);
            sc[nt][1] = __expf(sc[nt][1] - mn0);
            sc[nt][2] = __expf(sc[nt][2] - mn1);
            sc[nt][3] = __expf(sc[nt][3] - mn1);
            sum0 += sc[nt][0] + sc[nt][1];
            sum1 += sc[nt][2] + sc[nt][3];
        }
        sum0 += __shfl_xor_sync(0xffffffffu, sum0, 1);
        sum0 += __shfl_xor_sync(0xffffffffu, sum0, 2);
        sum1 += __shfl_xor_sync(0xffffffffu, sum1, 1);
        sum1 += __shfl_xor_sync(0xffffffffu, sum1, 2);

        l0r = l0r * c0 + sum0;
        l1r = l1r * c1 + sum1;
        m0r = mn0;
        m1r = mn1;

#pragma unroll
        for (int nt = 0; nt < 8; nt++) {
            o[nt][0] *= c0; o[nt][1] *= c0;
            o[nt][2] *= c1; o[nt][3] *= c1;
        }

        // ---- P V
#pragma unroll
        for (int ks = 0; ks < 4; ks++) {
            uint32_t ph[4], pl[4];
            split2(sc[2 * ks][0],     sc[2 * ks][1],     ph[0], pl[0]);
            split2(sc[2 * ks][2],     sc[2 * ks][3],     ph[1], pl[1]);
            split2(sc[2 * ks + 1][0], sc[2 * ks + 1][1], ph[2], pl[2]);
            split2(sc[2 * ks + 1][2], sc[2 * ks + 1][3], ph[3], pl[3]);

            const int kr = ks * 16 + (lane & 15);
#pragma unroll
            for (int nt = 0; nt < 8; nt++) {
                uint32_t vh[2], vl[2];
                const uint32_t off = (uint32_t)(kr * 128 + ((nt ^ kr) & 7) * 16);
                ldm_x2t(vh, vb + off);
                ldm_x2t(vl, vb + 8192 + off);
                mma_bf16(o[nt], ph, vh);
                mma_bf16(o[nt], ph, vl);
                mma_bf16(o[nt], pl, vh);
            }
        }
        __syncthreads();
    }

    // ---- epilogue: write gA hi/lo (bf16 split of normalized output)
    const float inv0 = 1.f / l0r;
    const float inv1 = 1.f / l1r;
    const int b = bh >> 4, h = bh & 15;
    const int t0 = q0 + row0;
#pragma unroll
    for (int nt = 0; nt < 8; nt++) {
        const int col = h * DH + nt * 8 + (lane & 3) * 2;
        uint32_t hi, lo;
        split2(o[nt][0] * inv0, o[nt][1] * inv0, hi, lo);
        *(uint32_t*)(gAh + (size_t)(b * TT + t0) * DD + col) = hi;
        *(uint32_t*)(gAl + (size_t)(b * TT + t0) * DD + col) = lo;
        split2(o[nt][2] * inv1, o[nt][3] * inv1, hi, lo);
        *(uint32_t*)(gAh + (size_t)(b * TT + t0 + 8) * DD + col) = hi;
        *(uint32_t*)(gAl + (size_t)(b * TT + t0 + 8) * DD + col) = lo;
    }
}

// ---------------------------------------------------------------------------
// Launcher
// ---------------------------------------------------------------------------
extern "C" void kernel_launch(void* const* d_in, const int* in_sizes, int n_in,
                              void* d_out, int out_size)
{
    const float* x      = (const float*)d_in[0];
    const float* W_attn = (const float*)d_in[1];
    const float* b_attn = (const float*)d_in[2];
    const float* W_proj = (const float*)d_in[3];
    const float* b_proj = (const float*)d_in[4];
    float* out = (float*)d_out;

    cudaFuncSetAttribute(gemm2<0>, cudaFuncAttributeMaxDynamicSharedMemorySize, 131072);
    cudaFuncSetAttribute(gemm2<1>, cudaFuncAttributeMaxDynamicSharedMemorySize, 131072);
    cudaFuncSetAttribute(flash2,   cudaFuncAttributeMaxDynamicSharedMemorySize, 81920);

    prep_split<0><<<(MM * DD / 4 + 255) / 256, 256>>>((const float4*)x, MM * DD / 4);
    prep_split<1><<<(DD * N_QKV / 4 + 255) / 256, 256>>>((const float4*)W_attn, DD * N_QKV / 4);
    prep_split<2><<<(DD * DD / 4 + 255) / 256, 256>>>((const float4*)W_proj, DD * DD / 4);

    dim3 g1(N_QKV / BN, MM / BM);       // 24 x 32
    gemm2<0><<<g1, 256, 131072>>>(b_attn, nullptr);

    dim3 g2(BB * HH, TT / 64);          // 32 x 32
    flash2<<<g2, 128, 81920>>>();

    dim3 g3(DD / BN, MM / BM);          // 8 x 32
    gemm2<1><<<g3, 256, 131072>>>(b_proj, out);
}

// round 7
// speedup vs baseline: 4.4654x; 1.1080x over previous
#include <cuda_runtime.h>
#include <cuda_bf16.h>
#include <cstdint>

// Problem constants
#define BB 2
#define TT 2048
#define DD 1024
#define HH 16
#define DH 64
#define MM (BB*TT)          // 4096
#define N_QKV (3*DD)        // 3072

// ---------------------------------------------------------------------------
// Persistent split-bf16 scratch (device globals — no runtime allocation)
// ---------------------------------------------------------------------------
__device__ __align__(16) __nv_bfloat16 Xh[MM*DD],  Xl[MM*DD];
__device__ __align__(16) __nv_bfloat16 Wah[DD*N_QKV], Wal[DD*N_QKV];
__device__ __align__(16) __nv_bfloat16 Wph[DD*DD], Wpl[DD*DD];
__device__ __align__(16) __nv_bfloat16 gQh[BB*HH*TT*DH], gQl[BB*HH*TT*DH];
__device__ __align__(16) __nv_bfloat16 gKh[BB*HH*TT*DH], gKl[BB*HH*TT*DH];
__device__ __align__(16) __nv_bfloat16 gVh[BB*HH*TT*DH], gVl[BB*HH*TT*DH];
__device__ __align__(16) __nv_bfloat16 gAh[MM*DD], gAl[MM*DD];

// ---------------------------------------------------------------------------
// Helpers (baseline PTX: ldmatrix, mma.sync, cp.async — all sm_80)
// ---------------------------------------------------------------------------
__device__ __forceinline__ uint32_t smem_u32(const void* p) {
    uint32_t a;
    asm("{ .reg .u64 t; cvta.to.shared.u64 t, %1; cvt.u32.u64 %0, t; }"
        : "=r"(a) : "l"(p));
    return a;
}

__device__ __forceinline__ void ldm_x4(uint32_t* r, uint32_t addr) {
    asm volatile("ldmatrix.sync.aligned.m8n8.x4.shared.b16 {%0,%1,%2,%3}, [%4];"
                 : "=r"(r[0]), "=r"(r[1]), "=r"(r[2]), "=r"(r[3]) : "r"(addr));
}
__device__ __forceinline__ void ldm_x2(uint32_t* r, uint32_t addr) {
    asm volatile("ldmatrix.sync.aligned.m8n8.x2.shared.b16 {%0,%1}, [%2];"
                 : "=r"(r[0]), "=r"(r[1]) : "r"(addr));
}
__device__ __forceinline__ void ldm_x2t(uint32_t* r, uint32_t addr) {
    asm volatile("ldmatrix.sync.aligned.m8n8.x2.trans.shared.b16 {%0,%1}, [%2];"
                 : "=r"(r[0]), "=r"(r[1]) : "r"(addr));
}
__device__ __forceinline__ void mma_bf16(float* c, const uint32_t* a, const uint32_t* b) {
    asm volatile(
        "mma.sync.aligned.m16n8k16.row.col.f32.bf16.bf16.f32 "
        "{%0,%1,%2,%3}, {%4,%5,%6,%7}, {%8,%9}, {%0,%1,%2,%3};"
        : "+f"(c[0]), "+f"(c[1]), "+f"(c[2]), "+f"(c[3])
        : "r"(a[0]), "r"(a[1]), "r"(a[2]), "r"(a[3]), "r"(b[0]), "r"(b[1]));
}
__device__ __forceinline__ uint32_t pack_bf2(__nv_bfloat16 a, __nv_bfloat16 b) {
    __nv_bfloat162 t(a, b);
    return *reinterpret_cast<uint32_t*>(&t);
}
__device__ __forceinline__ void split2(float x, float y, uint32_t& hi, uint32_t& lo) {
    __nv_bfloat16 hx = __float2bfloat16(x);
    __nv_bfloat16 hy = __float2bfloat16(y);
    __nv_bfloat16 lx = __float2bfloat16(x - __bfloat162float(hx));
    __nv_bfloat16 ly = __float2bfloat16(y - __bfloat162float(hy));
    hi = pack_bf2(hx, hy);
    lo = pack_bf2(lx, ly);
}
__device__ __forceinline__ void cp16(uint32_t dst, const void* src) {
    asm volatile("cp.async.cg.shared.global [%0], [%1], 16;"
                 :: "r"(dst), "l"(src) : "memory");
}
#define CP_COMMIT() asm volatile("cp.async.commit_group;" ::: "memory")
#define CP_WAIT1()  asm volatile("cp.async.wait_group 1;" ::: "memory")
#define CP_WAIT0()  asm volatile("cp.async.wait_group 0;" ::: "memory")

// ---------------------------------------------------------------------------
// Prep: f32 -> bf16 hi/lo split (vectorized)
// ---------------------------------------------------------------------------
template <int WHICH>
__global__ void prep_split(const float4* __restrict__ in, int n4)
{
    __nv_bfloat16* oh = (WHICH == 0) ? Xh : ((WHICH == 1) ? Wah : Wph);
    __nv_bfloat16* ol = (WHICH == 0) ? Xl : ((WHICH == 1) ? Wal : Wpl);
    const int i = blockIdx.x * blockDim.x + threadIdx.x;
    if (i < n4) {
        float4 v = __ldg(in + i);
        uint32_t h0, l0, h1, l1;
        split2(v.x, v.y, h0, l0);
        split2(v.z, v.w, h1, l1);
        ((uint2*)oh)[i] = make_uint2(h0, h1);
        ((uint2*)ol)[i] = make_uint2(l0, l1);
    }
}

// ---------------------------------------------------------------------------
// Pipelined split-bf16 tensor-core GEMM. Tile 128x128, BK=64, 2-stage cp.async.
// 512 threads / 16 warps (4x4), warp tile 32x32 — 4 warps/SMSP for latency.
// ---------------------------------------------------------------------------
#define BM 128
#define BN 128
#define GSTG 65536

template <int MODE>
__global__ __launch_bounds__(512, 1) void gemm2(
    const float* __restrict__ bias, float* __restrict__ C)
{
    extern __shared__ char smem[];
    const uint32_t sbase = smem_u32(smem);
    const __nv_bfloat16* Ah = (MODE == 0) ? Xh : gAh;
    const __nv_bfloat16* Al = (MODE == 0) ? Xl : gAl;
    const __nv_bfloat16* Bh = (MODE == 0) ? Wah : Wph;
    const __nv_bfloat16* Bl = (MODE == 0) ? Wal : Wpl;
    const int Nn = (MODE == 0) ? N_QKV : DD;
    const int n0 = blockIdx.x * BN;
    const int m0 = blockIdx.y * BM;
    const int tid = threadIdx.x;
    const int lane = tid & 31;
    const int wid = tid >> 5;
    const int wm = wid & 3;       // rows wm*32
    const int wn = wid >> 2;      // cols wn*32

    auto issue = [&](int step) {
        const uint32_t sb = sbase + (step & 1) * GSTG;
        const int k0 = step * 64;
        {   // A tile: 128 rows x 64 bf16 (hi + lo); 4 threads/row, 2 chunks each
            const int r = tid >> 2, c0 = (tid & 3) * 2;
            const __nv_bfloat16* sh = Ah + (size_t)(m0 + r) * DD + k0 + c0 * 8;
            const __nv_bfloat16* sl = Al + (size_t)(m0 + r) * DD + k0 + c0 * 8;
            const uint32_t db = sb + r * 128;
#pragma unroll
            for (int i = 0; i < 2; i++) {
                const int c = c0 + i;
                const uint32_t sw = (uint32_t)(((c ^ r) & 7) * 16);
                cp16(db + sw, sh + i * 8);
                cp16(db + 16384 + sw, sl + i * 8);
            }
        }
        {   // B tile: 64 rows x 128 bf16 (hi + lo); 8 threads/row, 2 chunks each
            const int r = tid >> 3, c0 = (tid & 7) * 2;
            const __nv_bfloat16* sh = Bh + (size_t)(k0 + r) * Nn + n0 + c0 * 8;
            const __nv_bfloat16* sl = Bl + (size_t)(k0 + r) * Nn + n0 + c0 * 8;
            const uint32_t db = sb + 32768 + r * 256;
#pragma unroll
            for (int i = 0; i < 2; i++) {
                const int c = c0 + i;
                const uint32_t sw = (uint32_t)((((c & 8) | ((c ^ r) & 7))) * 16);
                cp16(db + sw, sh + i * 8);
                cp16(db + 16384 + sw, sl + i * 8);
            }
        }
    };

    float acc[2][4][4];
#pragma unroll
    for (int mt = 0; mt < 2; mt++)
#pragma unroll
        for (int nt = 0; nt < 4; nt++)
#pragma unroll
            for (int e = 0; e < 4; e++) acc[mt][nt][e] = 0.f;

    issue(0); CP_COMMIT();

    for (int step = 0; step < 16; step++) {
        if (step + 1 < 16) { issue(step + 1); CP_COMMIT(); CP_WAIT1(); }
        else               { CP_WAIT0(); }
        __syncthreads();

        const uint32_t sb = sbase + (step & 1) * GSTG;
#pragma unroll
        for (int kk = 0; kk < 4; kk++) {
            uint32_t ah[2][4], al[2][4];
            const int rb = wm * 32 + (lane & 7) + ((lane >> 3) & 1) * 8;
            const int ch = kk * 2 + (lane >> 4);
#pragma unroll
            for (int mt = 0; mt < 2; mt++) {
                const int r = rb + mt * 16;
                const uint32_t off = (uint32_t)(r * 128 + ((ch ^ r) & 7) * 16);
                ldm_x4(ah[mt], sb + off);
                ldm_x4(al[mt], sb + 16384 + off);
            }
            uint32_t bh[4][2], bl[4][2];
            const int kr = kk * 16 + (lane & 15);
#pragma unroll
            for (int nt = 0; nt < 4; nt++) {
                const int cB = wn * 4 + nt;
                const uint32_t off =
                    (uint32_t)(kr * 256 + ((cB & 8) | ((cB ^ kr) & 7)) * 16);
                ldm_x2t(bh[nt], sb + 32768 + off);
                ldm_x2t(bl[nt], sb + 49152 + off);
            }
#pragma unroll
            for (int mt = 0; mt < 2; mt++)
#pragma unroll
                for (int nt = 0; nt < 4; nt++) {
                    mma_bf16(acc[mt][nt], ah[mt], bh[nt]);
                    mma_bf16(acc[mt][nt], ah[mt], bl[nt]);
                    mma_bf16(acc[mt][nt], al[mt], bh[nt]);
                }
        }
        __syncthreads();
    }

    // epilogue
#pragma unroll
    for (int mt = 0; mt < 2; mt++) {
        const int rb = m0 + wm * 32 + mt * 16 + (lane >> 2);
#pragma unroll
        for (int nt = 0; nt < 4; nt++) {
            const int col = n0 + wn * 32 + nt * 8 + (lane & 3) * 2;
            const float2 bv = *(const float2*)(bias + col);
#pragma unroll
            for (int rr = 0; rr < 2; rr++) {
                const int m = rb + rr * 8;
                float vx = acc[mt][nt][rr * 2 + 0] + bv.x;
                float vy = acc[mt][nt][rr * 2 + 1] + bv.y;
                if (MODE == 0) {
                    const int which = col >> 10;
                    if (which == 0) { vx *= 0.125f; vy *= 0.125f; }   // Q pre-scale
                    const int h = (col & (DD - 1)) >> 6;
                    const int dd = col & (DH - 1);
                    const int b = m >> 11, t = m & (TT - 1);
                    const size_t idx = (((size_t)(b * HH + h) * TT) + t) * DH + dd;
                    uint32_t hi, lo;
                    split2(vx, vy, hi, lo);
                    __nv_bfloat16 *dh, *dl;
                    if (which == 0)      { dh = gQh; dl = gQl; }
                    else if (which == 1) { dh = gKh; dl = gKl; }
                    else                 { dh = gVh; dl = gVl; }
                    *(uint32_t*)(dh + idx) = hi;
                    *(uint32_t*)(dl + idx) = lo;
                } else {
                    *(float2*)(C + (size_t)m * DD + col) = make_float2(vx, vy);
                }
            }
        }
    }
}

// ---------------------------------------------------------------------------
// Tensor-core flash attention on pre-split bf16 Q/K/V (unchanged from R6).
// ---------------------------------------------------------------------------
#define FSTG 32768

__global__ __launch_bounds__(128) void flash2()
{
    extern __shared__ char smem[];
    const uint32_t sbase = smem_u32(smem);
    const int bh = blockIdx.x;
    const int qt = gridDim.y - 1 - blockIdx.y;      // big tiles first
    const int q0 = qt * 64;
    const int tid = threadIdx.x;
    const int lane = tid & 31;
    const int wq = tid >> 5;
    const size_t hoff = (size_t)bh * TT * DH;

    {
        const int r = tid >> 1, cb = (tid & 1) * 4;
        const size_t go = hoff + (size_t)(q0 + r) * DH + cb * 8;
        const uint32_t db = sbase + r * 128;
#pragma unroll
        for (int i = 0; i < 4; i++) {
            const int c = cb + i;
            const uint32_t sw = (uint32_t)(((c ^ r) & 7) * 16);
            cp16(db + sw, gQh + go + i * 8);
            cp16(db + 8192 + sw, gQl + go + i * 8);
        }
    }
    CP_COMMIT();

    auto issueKV = [&](int jt) {
        const uint32_t db0 = sbase + 16384 + (jt & 1) * FSTG;
        const int j0 = jt * 64;
        const int r = tid >> 1, cb = (tid & 1) * 4;
        const size_t go = hoff + (size_t)(j0 + r) * DH + cb * 8;
        const uint32_t db = db0 + r * 128;
#pragma unroll
        for (int i = 0; i < 4; i++) {
            const int c = cb + i;
            const uint32_t sw = (uint32_t)(((c ^ r) & 7) * 16);
            cp16(db + sw,         gKh + go + i * 8);
            cp16(db + 8192 + sw,  gKl + go + i * 8);
            cp16(db + 16384 + sw, gVh + go + i * 8);
            cp16(db + 24576 + sw, gVl + go + i * 8);
        }
    };

    issueKV(0); CP_COMMIT();
    CP_WAIT1(); __syncthreads();

    uint32_t qh[4][4], ql[4][4];
    {
        const int r = wq * 16 + (lane & 7) + ((lane >> 3) & 1) * 8;
#pragma unroll
        for (int ks = 0; ks < 4; ks++) {
            const int ch = ks * 2 + (lane >> 4);
            const uint32_t off = (uint32_t)(r * 128 + ((ch ^ r) & 7) * 16);
            ldm_x4(qh[ks], sbase + off);
            ldm_x4(ql[ks], sbase + 8192 + off);
        }
    }

    float o[8][4];
#pragma unroll
    for (int nt = 0; nt < 8; nt++)
#pragma unroll
        for (int e = 0; e < 4; e++) o[nt][e] = 0.f;
    float m0r = -1e30f, m1r = -1e30f, l0r = 0.f, l1r = 0.f;
    const int row0 = wq * 16 + (lane >> 2);

    for (int jt = 0; jt <= qt; jt++) {
        if (jt + 1 <= qt) { issueKV(jt + 1); CP_COMMIT(); CP_WAIT1(); }
        else              { CP_WAIT0(); }
        __syncthreads();

        const uint32_t kb = sbase + 16384 + (jt & 1) * FSTG;
        const uint32_t vb = kb + 16384;

        float sc[8][4];
#pragma unroll
        for (int nt = 0; nt < 8; nt++)
#pragma unroll
            for (int e = 0; e < 4; e++) sc[nt][e] = 0.f;

#pragma unroll
        for (int ks = 0; ks < 4; ks++) {
            uint32_t bh2[8][2], bl2[8][2];
            const int ln = lane & 15;
            const int ch = ks * 2 + ((ln >> 3) & 1);
#pragma unroll
            for (int nt = 0; nt < 8; nt++) {
                const int r = nt * 8 + (ln & 7);
                const uint32_t off = (uint32_t)(r * 128 + ((ch ^ r) & 7) * 16);
                ldm_x2(bh2[nt], kb + off);
                ldm_x2(bl2[nt], kb + 8192 + off);
            }
#pragma unroll
            for (int nt = 0; nt < 8; nt++) {
                mma_bf16(sc[nt], qh[ks], bh2[nt]);
                mma_bf16(sc[nt], qh[ks], bl2[nt]);
                mma_bf16(sc[nt], ql[ks], bh2[nt]);
            }
        }

        if (jt == qt) {
            const int cbase = (lane & 3) * 2;
#pragma unroll
            for (int nt = 0; nt < 8; nt++) {
                const int c0 = nt * 8 + cbase;
                if (c0 > row0)         sc[nt][0] = -1e30f;
                if (c0 + 1 > row0)     sc[nt][1] = -1e30f;
                if (c0 > row0 + 8)     sc[nt][2] = -1e30f;
                if (c0 + 1 > row0 + 8) sc[nt][3] = -1e30f;
            }
        }

        float mx0 = -1e30f, mx1 = -1e30f;
#pragma unroll
        for (int nt = 0; nt < 8; nt++) {
            mx0 = fmaxf(mx0, fmaxf(sc[nt][0], sc[nt][1]));
            mx1 = fmaxf(mx1, fmaxf(sc[nt][2], sc[nt][3]));
        }
        mx0 = fmaxf(mx0, __shfl_xor_sync(0xffffffffu, mx0, 1));
        mx0 = fmaxf(mx0, __shfl_xor_sync(0xffffffffu, mx0, 2));
        mx1 = fmaxf(mx1, __shfl_xor_sync(0xffffffffu, mx1, 1));
        mx1 = fmaxf(mx1, __shfl_xor_sync(0xffffffffu, mx1, 2));

        const float mn0 = fmaxf(m0r, mx0);
        const float mn1 = fmaxf(m1r, mx1);
        const float c0 = __expf(m0r - mn0);
        const float c1 = __expf(m1r - mn1);

        float sum0 = 0.f, sum1 = 0.f;
#pragma unroll
        for (int nt = 0; nt < 8; nt++) {
            sc[nt][0] = __expf(sc[nt][0] - mn0);
            sc[nt][1] = __expf(sc[nt][1] - mn0);
            sc[nt][2] = __expf(sc[nt][2] - mn1);
            sc[nt][3] = __expf(sc[nt][3] - mn1);
            sum0 += sc[nt][0] + sc[nt][1];
            sum1 += sc[nt][2] + sc[nt][3];
        }
        sum0 += __shfl_xor_sync(0xffffffffu, sum0, 1);
        sum0 += __shfl_xor_sync(0xffffffffu, sum0, 2);
        sum1 += __shfl_xor_sync(0xffffffffu, sum1, 1);
        sum1 += __shfl_xor_sync(0xffffffffu, sum1, 2);

        l0r = l0r * c0 + sum0;
        l1r = l1r * c1 + sum1;
        m0r = mn0;
        m1r = mn1;

#pragma unroll
        for (int nt = 0; nt < 8; nt++) {
            o[nt][0] *= c0; o[nt][1] *= c0;
            o[nt][2] *= c1; o[nt][3] *= c1;
        }

#pragma unroll
        for (int ks = 0; ks < 4; ks++) {
            uint32_t ph[4], pl[4];
            split2(sc[2 * ks][0],     sc[2 * ks][1],     ph[0], pl[0]);
            split2(sc[2 * ks][2],     sc[2 * ks][3],     ph[1], pl[1]);
            split2(sc[2 * ks + 1][0], sc[2 * ks + 1][1], ph[2], pl[2]);
            split2(sc[2 * ks + 1][2], sc[2 * ks + 1][3], ph[3], pl[3]);

            const int kr = ks * 16 + (lane & 15);
#pragma unroll
            for (int nt = 0; nt < 8; nt++) {
                uint32_t vh[2], vl[2];
                const uint32_t off = (uint32_t)(kr * 128 + ((nt ^ kr) & 7) * 16);
                ldm_x2t(vh, vb + off);
                ldm_x2t(vl, vb + 8192 + off);
                mma_bf16(o[nt], ph, vh);
                mma_bf16(o[nt], ph, vl);
                mma_bf16(o[nt], pl, vh);
            }
        }
        __syncthreads();
    }

    const float inv0 = 1.f / l0r;
    const float inv1 = 1.f / l1r;
    const int b = bh >> 4, h = bh & 15;
    const int t0 = q0 + row0;
#pragma unroll
    for (int nt = 0; nt < 8; nt++) {
        const int col = h * DH + nt * 8 + (lane & 3) * 2;
        uint32_t hi, lo;
        split2(o[nt][0] * inv0, o[nt][1] * inv0, hi, lo);
        *(uint32_t*)(gAh + (size_t)(b * TT + t0) * DD + col) = hi;
        *(uint32_t*)(gAl + (size_t)(b * TT + t0) * DD + col) = lo;
        split2(o[nt][2] * inv1, o[nt][3] * inv1, hi, lo);
        *(uint32_t*)(gAh + (size_t)(b * TT + t0 + 8) * DD + col) = hi;
        *(uint32_t*)(gAl + (size_t)(b * TT + t0 + 8) * DD + col) = lo;
    }
}

// ---------------------------------------------------------------------------
// Launcher
// ---------------------------------------------------------------------------
extern "C" void kernel_launch(void* const* d_in, const int* in_sizes, int n_in,
                              void* d_out, int out_size)
{
    const float* x      = (const float*)d_in[0];
    const float* W_attn = (const float*)d_in[1];
    const float* b_attn = (const float*)d_in[2];
    const float* W_proj = (const float*)d_in[3];
    const float* b_proj = (const float*)d_in[4];
    float* out = (float*)d_out;

    cudaFuncSetAttribute(gemm2<0>, cudaFuncAttributeMaxDynamicSharedMemorySize, 131072);
    cudaFuncSetAttribute(gemm2<1>, cudaFuncAttributeMaxDynamicSharedMemorySize, 131072);
    cudaFuncSetAttribute(flash2,   cudaFuncAttributeMaxDynamicSharedMemorySize, 81920);

    prep_split<0><<<(MM * DD / 4 + 255) / 256, 256>>>((const float4*)x, MM * DD / 4);
    prep_split<1><<<(DD * N_QKV / 4 + 255) / 256, 256>>>((const float4*)W_attn, DD * N_QKV / 4);
    prep_split<2><<<(DD * DD / 4 + 255) / 256, 256>>>((const float4*)W_proj, DD * DD / 4);

    dim3 g1(N_QKV / BN, MM / BM);       // 24 x 32
    gemm2<0><<<g1, 512, 131072>>>(b_attn, nullptr);

    dim3 g2(BB * HH, TT / 64);          // 32 x 32
    flash2<<<g2, 128, 81920>>>();

    dim3 g3(DD / BN, MM / BM);          // 8 x 32
    gemm2<1><<<g3, 512, 131072>>>(b_proj, out);
}

// round 9
// speedup vs baseline: 4.6622x; 1.0441x over previous
#include <cuda_runtime.h>
#include <cuda_bf16.h>
#include <cstdint>

// Problem constants
#define BB 2
#define TT 2048
#define DD 1024
#define HH 16
#define DH 64
#define MM (BB*TT)          // 4096
#define N_QKV (3*DD)        // 3072

// ---------------------------------------------------------------------------
// Persistent split-bf16 scratch (device globals — no runtime allocation)
// ---------------------------------------------------------------------------
__device__ __align__(16) __nv_bfloat16 Xh[MM*DD],  Xl[MM*DD];
__device__ __align__(16) __nv_bfloat16 Wah[DD*N_QKV], Wal[DD*N_QKV];
__device__ __align__(16) __nv_bfloat16 Wph[DD*DD], Wpl[DD*DD];
__device__ __align__(16) __nv_bfloat16 gQh[BB*HH*TT*DH], gQl[BB*HH*TT*DH];
__device__ __align__(16) __nv_bfloat16 gKh[BB*HH*TT*DH], gKl[BB*HH*TT*DH];
__device__ __align__(16) __nv_bfloat16 gVh[BB*HH*TT*DH], gVl[BB*HH*TT*DH];
__device__ __align__(16) __nv_bfloat16 gAh[MM*DD], gAl[MM*DD];

// ---------------------------------------------------------------------------
// Helpers (baseline PTX: ldmatrix, mma.sync, cp.async — all sm_80)
// ---------------------------------------------------------------------------
__device__ __forceinline__ uint32_t smem_u32(const void* p) {
    uint32_t a;
    asm("{ .reg .u64 t; cvta.to.shared.u64 t, %1; cvt.u32.u64 %0, t; }"
        : "=r"(a) : "l"(p));
    return a;
}

__device__ __forceinline__ void ldm_x4(uint32_t* r, uint32_t addr) {
    asm volatile("ldmatrix.sync.aligned.m8n8.x4.shared.b16 {%0,%1,%2,%3}, [%4];"
                 : "=r"(r[0]), "=r"(r[1]), "=r"(r[2]), "=r"(r[3]) : "r"(addr));
}
__device__ __forceinline__ void ldm_x2(uint32_t* r, uint32_t addr) {
    asm volatile("ldmatrix.sync.aligned.m8n8.x2.shared.b16 {%0,%1}, [%2];"
                 : "=r"(r[0]), "=r"(r[1]) : "r"(addr));
}
__device__ __forceinline__ void ldm_x2t(uint32_t* r, uint32_t addr) {
    asm volatile("ldmatrix.sync.aligned.m8n8.x2.trans.shared.b16 {%0,%1}, [%2];"
                 : "=r"(r[0]), "=r"(r[1]) : "r"(addr));
}
__device__ __forceinline__ void mma_bf16(float* c, const uint32_t* a, const uint32_t* b) {
    asm volatile(
        "mma.sync.aligned.m16n8k16.row.col.f32.bf16.bf16.f32 "
        "{%0,%1,%2,%3}, {%4,%5,%6,%7}, {%8,%9}, {%0,%1,%2,%3};"
        : "+f"(c[0]), "+f"(c[1]), "+f"(c[2]), "+f"(c[3])
        : "r"(a[0]), "r"(a[1]), "r"(a[2]), "r"(a[3]), "r"(b[0]), "r"(b[1]));
}
__device__ __forceinline__ uint32_t pack_bf2(__nv_bfloat16 a, __nv_bfloat16 b) {
    __nv_bfloat162 t(a, b);
    return *reinterpret_cast<uint32_t*>(&t);
}
__device__ __forceinline__ void split2(float x, float y, uint32_t& hi, uint32_t& lo) {
    __nv_bfloat16 hx = __float2bfloat16(x);
    __nv_bfloat16 hy = __float2bfloat16(y);
    __nv_bfloat16 lx = __float2bfloat16(x - __bfloat162float(hx));
    __nv_bfloat16 ly = __float2bfloat16(y - __bfloat162float(hy));
    hi = pack_bf2(hx, hy);
    lo = pack_bf2(lx, ly);
}
__device__ __forceinline__ void cp16(uint32_t dst, const void* src) {
    asm volatile("cp.async.cg.shared.global [%0], [%1], 16;"
                 :: "r"(dst), "l"(src) : "memory");
}
#define CP_COMMIT() asm volatile("cp.async.commit_group;" ::: "memory")
#define CP_WAIT1()  asm volatile("cp.async.wait_group 1;" ::: "memory")
#define CP_WAIT0()  asm volatile("cp.async.wait_group 0;" ::: "memory")

// ---------------------------------------------------------------------------
// Prep: f32 -> bf16 hi/lo split (vectorized)
// ---------------------------------------------------------------------------
template <int WHICH>
__global__ void prep_split(const float4* __restrict__ in, int n4)
{
    __nv_bfloat16* oh = (WHICH == 0) ? Xh : ((WHICH == 1) ? Wah : Wph);
    __nv_bfloat16* ol = (WHICH == 0) ? Xl : ((WHICH == 1) ? Wal : Wpl);
    const int i = blockIdx.x * blockDim.x + threadIdx.x;
    if (i < n4) {
        float4 v = __ldg(in + i);
        uint32_t h0, l0, h1, l1;
        split2(v.x, v.y, h0, l0);
        split2(v.z, v.w, h1, l1);
        ((uint2*)oh)[i] = make_uint2(h0, h1);
        ((uint2*)ol)[i] = make_uint2(l0, l1);
    }
}

// ---------------------------------------------------------------------------
// Pipelined split-bf16 tensor-core GEMM. Tile 128x128, BK=64.
// 3-stage cp.async (3 x 64KB = 192KB smem) -> ONE __syncthreads per K-step.
// 512 threads / 16 warps (4x4), warp tile 32x32.
// ---------------------------------------------------------------------------
#define BM 128
#define BN 128
#define GSTG 65536
#define GSMEM (3 * GSTG)

template <int MODE>
__global__ __launch_bounds__(512, 1) void gemm2(
    const float* __restrict__ bias, float* __restrict__ C)
{
    extern __shared__ char smem[];
    const uint32_t sbase = smem_u32(smem);
    const __nv_bfloat16* Ah = (MODE == 0) ? Xh : gAh;
    const __nv_bfloat16* Al = (MODE == 0) ? Xl : gAl;
    const __nv_bfloat16* Bh = (MODE == 0) ? Wah : Wph;
    const __nv_bfloat16* Bl = (MODE == 0) ? Wal : Wpl;
    const int Nn = (MODE == 0) ? N_QKV : DD;
    const int n0 = blockIdx.x * BN;
    const int m0 = blockIdx.y * BM;
    const int tid = threadIdx.x;
    const int lane = tid & 31;
    const int wid = tid >> 5;
    const int wm = wid & 3;       // rows wm*32
    const int wn = wid >> 2;      // cols wn*32

    auto issue = [&](int step) {
        const uint32_t sb = sbase + (step % 3) * GSTG;
        const int k0 = step * 64;
        {   // A tile: 128 rows x 64 bf16 (hi + lo); 4 threads/row, 2 chunks each
            const int r = tid >> 2, c0 = (tid & 3) * 2;
            const __nv_bfloat16* sh = Ah + (size_t)(m0 + r) * DD + k0 + c0 * 8;
            const __nv_bfloat16* sl = Al + (size_t)(m0 + r) * DD + k0 + c0 * 8;
            const uint32_t db = sb + r * 128;
#pragma unroll
            for (int i = 0; i < 2; i++) {
                const int c = c0 + i;
                const uint32_t sw = (uint32_t)(((c ^ r) & 7) * 16);
                cp16(db + sw, sh + i * 8);
                cp16(db + 16384 + sw, sl + i * 8);
            }
        }
        {   // B tile: 64 rows x 128 bf16 (hi + lo); 8 threads/row, 2 chunks each
            const int r = tid >> 3, c0 = (tid & 7) * 2;
            const __nv_bfloat16* sh = Bh + (size_t)(k0 + r) * Nn + n0 + c0 * 8;
            const __nv_bfloat16* sl = Bl + (size_t)(k0 + r) * Nn + n0 + c0 * 8;
            const uint32_t db = sb + 32768 + r * 256;
#pragma unroll
            for (int i = 0; i < 2; i++) {
                const int c = c0 + i;
                const uint32_t sw = (uint32_t)((((c & 8) | ((c ^ r) & 7))) * 16);
                cp16(db + sw, sh + i * 8);
                cp16(db + 16384 + sw, sl + i * 8);
            }
        }
    };

    float acc[2][4][4];
#pragma unroll
    for (int mt = 0; mt < 2; mt++)
#pragma unroll
        for (int nt = 0; nt < 4; nt++)
#pragma unroll
            for (int e = 0; e < 4; e++) acc[mt][nt][e] = 0.f;

    issue(0); CP_COMMIT();
    issue(1); CP_COMMIT();

    for (int step = 0; step < 16; step++) {
        if (step == 15) { CP_WAIT0(); } else { CP_WAIT1(); }
        __syncthreads();

        const uint32_t sb = sbase + (step % 3) * GSTG;
#pragma unroll
        for (int kk = 0; kk < 4; kk++) {
            uint32_t ah[2][4], al[2][4];
            const int rb = wm * 32 + (lane & 7) + ((lane >> 3) & 1) * 8;
            const int ch = kk * 2 + (lane >> 4);
#pragma unroll
            for (int mt = 0; mt < 2; mt++) {
                const int r = rb + mt * 16;
                const uint32_t off = (uint32_t)(r * 128 + ((ch ^ r) & 7) * 16);
                ldm_x4(ah[mt], sb + off);
                ldm_x4(al[mt], sb + 16384 + off);
            }
            uint32_t bh[4][2], bl[4][2];
            const int kr = kk * 16 + (lane & 15);
#pragma unroll
            for (int nt = 0; nt < 4; nt++) {
                const int cB = wn * 4 + nt;
                const uint32_t off =
                    (uint32_t)(kr * 256 + ((cB & 8) | ((cB ^ kr) & 7)) * 16);
                ldm_x2t(bh[nt], sb + 32768 + off);
                ldm_x2t(bl[nt], sb + 49152 + off);
            }
#pragma unroll
            for (int mt = 0; mt < 2; mt++)
#pragma unroll
                for (int nt = 0; nt < 4; nt++) {
                    mma_bf16(acc[mt][nt], ah[mt], bh[nt]);
                    mma_bf16(acc[mt][nt], ah[mt], bl[nt]);
                    mma_bf16(acc[mt][nt], al[mt], bh[nt]);
                }
        }

        if (step + 2 < 16) { issue(step + 2); CP_COMMIT(); }
    }

    // epilogue
#pragma unroll
    for (int mt = 0; mt < 2; mt++) {
        const int rb = m0 + wm * 32 + mt * 16 + (lane >> 2);
#pragma unroll
        for (int nt = 0; nt < 4; nt++) {
            const int col = n0 + wn * 32 + nt * 8 + (lane & 3) * 2;
            const float2 bv = *(const float2*)(bias + col);
#pragma unroll
            for (int rr = 0; rr < 2; rr++) {
                const int m = rb + rr * 8;
                float vx = acc[mt][nt][rr * 2 + 0] + bv.x;
                float vy = acc[mt][nt][rr * 2 + 1] + bv.y;
                if (MODE == 0) {
                    const int which = col >> 10;
                    if (which == 0) { vx *= 0.125f; vy *= 0.125f; }   // Q pre-scale
                    const int h = (col & (DD - 1)) >> 6;
                    const int dd = col & (DH - 1);
                    const int b = m >> 11, t = m & (TT - 1);
                    const size_t idx = (((size_t)(b * HH + h) * TT) + t) * DH + dd;
                    uint32_t hi, lo;
                    split2(vx, vy, hi, lo);
                    __nv_bfloat16 *dh, *dl;
                    if (which == 0)      { dh = gQh; dl = gQl; }
                    else if (which == 1) { dh = gKh; dl = gKl; }
                    else                 { dh = gVh; dl = gVl; }
                    *(uint32_t*)(dh + idx) = hi;
                    *(uint32_t*)(dl + idx) = lo;
                } else {
                    *(float2*)(C + (size_t)m * DD + col) = make_float2(vx, vy);
                }
            }
        }
    }
}

// ---------------------------------------------------------------------------
// Tensor-core flash attention on pre-split bf16 Q/K/V (unchanged from R6/R7).
// ---------------------------------------------------------------------------
#define FSTG 32768

__global__ __launch_bounds__(128) void flash2()
{
    extern __shared__ char smem[];
    const uint32_t sbase = smem_u32(smem);
    const int bh = blockIdx.x;
    const int qt = gridDim.y - 1 - blockIdx.y;      // big tiles first
    const int q0 = qt * 64;
    const int tid = threadIdx.x;
    const int lane = tid & 31;
    const int wq = tid >> 5;
    const size_t hoff = (size_t)bh * TT * DH;

    {
        const int r = tid >> 1, cb = (tid & 1) * 4;
        const size_t go = hoff + (size_t)(q0 + r) * DH + cb * 8;
        const uint32_t db = sbase + r * 128;
#pragma unroll
        for (int i = 0; i < 4; i++) {
            const int c = cb + i;
            const uint32_t sw = (uint32_t)(((c ^ r) & 7) * 16);
            cp16(db + sw, gQh + go + i * 8);
            cp16(db + 8192 + sw, gQl + go + i * 8);
        }
    }
    CP_COMMIT();

    auto issueKV = [&](int jt) {
        const uint32_t db0 = sbase + 16384 + (jt & 1) * FSTG;
        const int j0 = jt * 64;
        const int r = tid >> 1, cb = (tid & 1) * 4;
        const size_t go = hoff + (size_t)(j0 + r) * DH + cb * 8;
        const uint32_t db = db0 + r * 128;
#pragma unroll
        for (int i = 0; i < 4; i++) {
            const int c = cb + i;
            const uint32_t sw = (uint32_t)(((c ^ r) & 7) * 16);
            cp16(db + sw,         gKh + go + i * 8);
            cp16(db + 8192 + sw,  gKl + go + i * 8);
            cp16(db + 16384 + sw, gVh + go + i * 8);
            cp16(db + 24576 + sw, gVl + go + i * 8);
        }
    };

    issueKV(0); CP_COMMIT();
    CP_WAIT1(); __syncthreads();

    uint32_t qh[4][4], ql[4][4];
    {
        const int r = wq * 16 + (lane & 7) + ((lane >> 3) & 1) * 8;
#pragma unroll
        for (int ks = 0; ks < 4; ks++) {
            const int ch = ks * 2 + (lane >> 4);
            const uint32_t off = (uint32_t)(r * 128 + ((ch ^ r) & 7) * 16);
            ldm_x4(qh[ks], sbase + off);
            ldm_x4(ql[ks], sbase + 8192 + off);
        }
    }

    float o[8][4];
#pragma unroll
    for (int nt = 0; nt < 8; nt++)
#pragma unroll
        for (int e = 0; e < 4; e++) o[nt][e] = 0.f;
    float m0r = -1e30f, m1r = -1e30f, l0r = 0.f, l1r = 0.f;
    const int row0 = wq * 16 + (lane >> 2);

    for (int jt = 0; jt <= qt; jt++) {
        if (jt + 1 <= qt) { issueKV(jt + 1); CP_COMMIT(); CP_WAIT1(); }
        else              { CP_WAIT0(); }
        __syncthreads();

        const uint32_t kb = sbase + 16384 + (jt & 1) * FSTG;
        const uint32_t vb = kb + 16384;

        float sc[8][4];
#pragma unroll
        for (int nt = 0; nt < 8; nt++)
#pragma unroll
            for (int e = 0; e < 4; e++) sc[nt][e] = 0.f;

#pragma unroll
        for (int ks = 0; ks < 4; ks++) {
            uint32_t bh2[8][2], bl2[8][2];
            const int ln = lane & 15;
            const int ch = ks * 2 + ((ln >> 3) & 1);
#pragma unroll
            for (int nt = 0; nt < 8; nt++) {
                const int r = nt * 8 + (ln & 7);
                const uint32_t off = (uint32_t)(r * 128 + ((ch ^ r) & 7) * 16);
                ldm_x2(bh2[nt], kb + off);
                ldm_x2(bl2[nt], kb + 8192 + off);
            }
#pragma unroll
            for (int nt = 0; nt < 8; nt++) {
                mma_bf16(sc[nt], qh[ks], bh2[nt]);
                mma_bf16(sc[nt], qh[ks], bl2[nt]);
                mma_bf16(sc[nt], ql[ks], bh2[nt]);
            }
        }

        if (jt == qt) {
            const int cbase = (lane & 3) * 2;
#pragma unroll
            for (int nt = 0; nt < 8; nt++) {
                const int c0 = nt * 8 + cbase;
                if (c0 > row0)         sc[nt][0] = -1e30f;
                if (c0 + 1 > row0)     sc[nt][1] = -1e30f;
                if (c0 > row0 + 8)     sc[nt][2] = -1e30f;
                if (c0 + 1 > row0 + 8) sc[nt][3] = -1e30f;
            }
        }

        float mx0 = -1e30f, mx1 = -1e30f;
#pragma unroll
        for (int nt = 0; nt < 8; nt++) {
            mx0 = fmaxf(mx0, fmaxf(sc[nt][0], sc[nt][1]));
            mx1 = fmaxf(mx1, fmaxf(sc[nt][2], sc[nt][3]));
        }
        mx0 = fmaxf(mx0, __shfl_xor_sync(0xffffffffu, mx0, 1));
        mx0 = fmaxf(mx0, __shfl_xor_sync(0xffffffffu, mx0, 2));
        mx1 = fmaxf(mx1, __shfl_xor_sync(0xffffffffu, mx1, 1));
        mx1 = fmaxf(mx1, __shfl_xor_sync(0xffffffffu, mx1, 2));

        const float mn0 = fmaxf(m0r, mx0);
        const float mn1 = fmaxf(m1r, mx1);
        const float c0 = __expf(m0r - mn0);
        const float c1 = __expf(m1r - mn1);

        float sum0 = 0.f, sum1 = 0.f;
#pragma unroll
        for (int nt = 0; nt < 8; nt++) {
            sc[nt][0] = __expf(sc[nt][0] - mn0);
            sc[nt][1] = __expf(sc[nt][1] - mn0);
            sc[nt][2] = __expf(sc[nt][2] - mn1);
            sc[nt][3] = __expf(sc[nt][3] - mn1);
            sum0 += sc[nt][0] + sc[nt][1];
            sum1 += sc[nt][2] + sc[nt][3];
        }
        sum0 += __shfl_xor_sync(0xffffffffu, sum0, 1);
        sum0 += __shfl_xor_sync(0xffffffffu, sum0, 2);
        sum1 += __shfl_xor_sync(0xffffffffu, sum1, 1);
        sum1 += __shfl_xor_sync(0xffffffffu, sum1, 2);

        l0r = l0r * c0 + sum0;
        l1r = l1r * c1 + sum1;
        m0r = mn0;
        m1r = mn1;

#pragma unroll
        for (int nt = 0; nt < 8; nt++) {
            o[nt][0] *= c0; o[nt][1] *= c0;
            o[nt][2] *= c1; o[nt][3] *= c1;
        }

#pragma unroll
        for (int ks = 0; ks < 4; ks++) {
            uint32_t ph[4], pl[4];
            split2(sc[2 * ks][0],     sc[2 * ks][1],     ph[0], pl[0]);
            split2(sc[2 * ks][2],     sc[2 * ks][3],     ph[1], pl[1]);
            split2(sc[2 * ks + 1][0], sc[2 * ks + 1][1], ph[2], pl[2]);
            split2(sc[2 * ks + 1][2], sc[2 * ks + 1][3], ph[3], pl[3]);

            const int kr = ks * 16 + (lane & 15);
#pragma unroll
            for (int nt = 0; nt < 8; nt++) {
                uint32_t vh[2], vl[2];
                const uint32_t off = (uint32_t)(kr * 128 + ((nt ^ kr) & 7) * 16);
                ldm_x2t(vh, vb + off);
                ldm_x2t(vl, vb + 8192 + off);
                mma_bf16(o[nt], ph, vh);
                mma_bf16(o[nt], ph, vl);
                mma_bf16(o[nt], pl, vh);
            }
        }
        __syncthreads();
    }

    const float inv0 = 1.f / l0r;
    const float inv1 = 1.f / l1r;
    const int b = bh >> 4, h = bh & 15;
    const int t0 = q0 + row0;
#pragma unroll
    for (int nt = 0; nt < 8; nt++) {
        const int col = h * DH + nt * 8 + (lane & 3) * 2;
        uint32_t hi, lo;
        split2(o[nt][0] * inv0, o[nt][1] * inv0, hi, lo);
        *(uint32_t*)(gAh + (size_t)(b * TT + t0) * DD + col) = hi;
        *(uint32_t*)(gAl + (size_t)(b * TT + t0) * DD + col) = lo;
        split2(o[nt][2] * inv1, o[nt][3] * inv1, hi, lo);
        *(uint32_t*)(gAh + (size_t)(b * TT + t0 + 8) * DD + col) = hi;
        *(uint32_t*)(gAl + (size_t)(b * TT + t0 + 8) * DD + col) = lo;
    }
}

// ---------------------------------------------------------------------------
// Launcher
// ---------------------------------------------------------------------------
extern "C" void kernel_launch(void* const* d_in, const int* in_sizes, int n_in,
                              void* d_out, int out_size)
{
    const float* x      = (const float*)d_in[0];
    const float* W_attn = (const float*)d_in[1];
    const float* b_attn = (const float*)d_in[2];
    const float* W_proj = (const float*)d_in[3];
    const float* b_proj = (const float*)d_in[4];
    float* out = (float*)d_out;

    cudaFuncSetAttribute(gemm2<0>, cudaFuncAttributeMaxDynamicSharedMemorySize, GSMEM);
    cudaFuncSetAttribute(gemm2<1>, cudaFuncAttributeMaxDynamicSharedMemorySize, GSMEM);
    cudaFuncSetAttribute(flash2,   cudaFuncAttributeMaxDynamicSharedMemorySize, 81920);

    prep_split<0><<<(MM * DD / 4 + 255) / 256, 256>>>((const float4*)x, MM * DD / 4);
    prep_split<1><<<(DD * N_QKV / 4 + 255) / 256, 256>>>((const float4*)W_attn, DD * N_QKV / 4);
    prep_split<2><<<(DD * DD / 4 + 255) / 256, 256>>>((const float4*)W_proj, DD * DD / 4);

    dim3 g1(N_QKV / BN, MM / BM);       // 24 x 32
    gemm2<0><<<g1, 512, GSMEM>>>(b_attn, nullptr);

    dim3 g2(BB * HH, TT / 64);          // 32 x 32
    flash2<<<g2, 128, 81920>>>();

    dim3 g3(DD / BN, MM / BM);          // 8 x 32
    gemm2<1><<<g3, 512, GSMEM>>>(b_proj, out);
}